// round 9
// baseline (speedup 1.0000x reference)
#include <cuda_runtime.h>
#include <cuda_bf16.h>
#include <math.h>
#include <stdint.h>

typedef signed char i8;

#define BQ 2
#define TQ 2048
#define DMODEL 1024
#define DINNER 2048
#define NHEADS 32
#define DHEAD 64
#define DCONV 4
#define PROJ_OUT 4224
#define BT 4096
#define PARAM_OFF 4096
#define BC_OFF 4160
#define DFF 4096

#define QMAXF 32512.f
#define SCF (256.f / (32512.f * 32512.f))

// ---------------- scratch (device globals; no allocation) ----------------
__device__ float g_proj[(size_t)BT * PROJ_OUT];
__device__ float g_val [(size_t)BT * DINNER];
__device__ float g_par [(size_t)BT * NHEADS * 2];
__device__ float g_bcT [(size_t)BT * 64];
__device__ float g_scan[(size_t)BT * DINNER];
__device__ float g_x1  [BT * DMODEL];
__device__ float g_ff  [(size_t)BT * DFF];
// int8 limb pairs (activations)
__device__ i8 g_xa[BT * DMODEL],         g_xb[BT * DMODEL];
__device__ i8 g_ga[(size_t)BT * DINNER], g_gb[(size_t)BT * DINNER];
__device__ i8 g_ha[BT * DMODEL],         g_hb[BT * DMODEL];
__device__ i8 g_fa[(size_t)BT * DFF],    g_fb[(size_t)BT * DFF];
// int8 limb pairs (weights)
__device__ i8 g_wina[PROJ_OUT * 1024],   g_winb[PROJ_OUT * 1024];
__device__ i8 g_woa [1024 * 2048],       g_wob [1024 * 2048];
__device__ i8 g_w1a [4096 * 1024],       g_w1b [4096 * 1024];
__device__ i8 g_w2a [1024 * 4096],       g_w2b [1024 * 4096];
// scales (row max)
__device__ float g_sx[BT], g_sg[BT], g_sh[BT], g_sf[BT];
__device__ float g_twin[PROJ_OUT], g_two[1024], g_tw1[4096], g_tw2[1024];

// ---------------- math helpers ----------------
__device__ __forceinline__ float sigmoidf_(float x) { return 1.f / (1.f + __expf(-x)); }
__device__ __forceinline__ float siluf_(float x)    { return x / (1.f + __expf(-x)); }
__device__ __forceinline__ float geluf_(float x) {
    float x3 = x * x * x;
    return 0.5f * x * (1.f + tanhf(0.7978845608028654f * (x + 0.044715f * x3)));
}
__device__ __forceinline__ float softplusf_(float x) {
    return (x > 20.f) ? x : log1pf(expf(x));
}

__device__ __forceinline__ float block_reduce_sum(float v) {
    __shared__ float sh[32];
    int lane = threadIdx.x & 31, wid = threadIdx.x >> 5;
    int nwarps = blockDim.x >> 5;
    #pragma unroll
    for (int m = 16; m > 0; m >>= 1) v += __shfl_xor_sync(0xffffffffu, v, m);
    if (lane == 0) sh[wid] = v;
    __syncthreads();
    if (wid == 0) {
        v = (lane < nwarps) ? sh[lane] : 0.f;
        #pragma unroll
        for (int m = 16; m > 0; m >>= 1) v += __shfl_xor_sync(0xffffffffu, v, m);
        if (lane == 0) sh[0] = v;
    }
    __syncthreads();
    return sh[0];
}
__device__ __forceinline__ float block_reduce_max(float v) {
    __shared__ float shm[32];
    int lane = threadIdx.x & 31, wid = threadIdx.x >> 5;
    int nwarps = blockDim.x >> 5;
    #pragma unroll
    for (int m = 16; m > 0; m >>= 1) v = fmaxf(v, __shfl_xor_sync(0xffffffffu, v, m));
    if (lane == 0) shm[wid] = v;
    __syncthreads();
    if (wid == 0) {
        v = (lane < nwarps) ? shm[lane] : 0.f;
        #pragma unroll
        for (int m = 16; m > 0; m >>= 1) v = fmaxf(v, __shfl_xor_sync(0xffffffffu, v, m));
        if (lane == 0) shm[0] = v;
    }
    __syncthreads();
    return shm[0];
}

// quantize value -> 2 int8 limbs (q = 256a + b)
__device__ __forceinline__ void quant2(float v, float qs, i8* a, i8* b) {
    int qi = (int)rintf(v * qs);
    int ai = (qi + 128) >> 8;
    int bi = qi - (ai << 8);
    *a = (i8)ai; *b = (i8)bi;
}

// ---------------- low-level ----------------
__device__ __forceinline__ uint32_t smem_u32(const void* p) {
    uint32_t a;
    asm("{ .reg .u64 t; cvta.to.shared.u64 t, %1; cvt.u32.u64 %0, t; }" : "=r"(a) : "l"(p));
    return a;
}
#define CP_ASYNC16(dst, src) \
    asm volatile("cp.async.cg.shared.global [%0], [%1], 16;" :: "r"((uint32_t)(dst)), "l"(src))
#define CP_COMMIT() asm volatile("cp.async.commit_group;" ::: "memory")

__device__ __forceinline__ void ldsm_x4(uint32_t* r, uint32_t addr) {
    asm volatile("ldmatrix.sync.aligned.m8n8.x4.shared.b16 {%0,%1,%2,%3}, [%4];"
                 : "=r"(r[0]), "=r"(r[1]), "=r"(r[2]), "=r"(r[3]) : "r"(addr));
}
__device__ __forceinline__ void ldsm_x2(uint32_t* r, uint32_t addr) {
    asm volatile("ldmatrix.sync.aligned.m8n8.x2.shared.b16 {%0,%1}, [%2];"
                 : "=r"(r[0]), "=r"(r[1]) : "r"(addr));
}
__device__ __forceinline__ void mma_s8(int* c, const uint32_t* a, const uint32_t* b) {
    asm volatile("mma.sync.aligned.m16n8k32.row.col.s32.s8.s8.s32 "
                 "{%0,%1,%2,%3}, {%4,%5,%6,%7}, {%8,%9}, {%0,%1,%2,%3};"
                 : "+r"(c[0]), "+r"(c[1]), "+r"(c[2]), "+r"(c[3])
                 : "r"(a[0]), "r"(a[1]), "r"(a[2]), "r"(a[3]), "r"(b[0]), "r"(b[1]));
}

// ---------------- weight quantization (per N-row) ----------------
__global__ void quant_w_kernel(const float* __restrict__ src, i8* __restrict__ qa,
                               i8* __restrict__ qb, float* __restrict__ scale, int K) {
    int row = blockIdx.x;
    const float* sr = src + (size_t)row * K;
    float mx = 0.f;
    for (int i = threadIdx.x; i < K; i += blockDim.x) mx = fmaxf(mx, fabsf(sr[i]));
    mx = block_reduce_max(mx);
    float S = fmaxf(mx, 1e-30f);
    if (threadIdx.x == 0) scale[row] = S;
    float qs = QMAXF / S;
    for (int i = threadIdx.x; i < K; i += blockDim.x)
        quant2(sr[i], qs, &qa[(size_t)row * K + i], &qb[(size_t)row * K + i]);
}

// ---------------- rmsnorm + quantize ----------------
__global__ void rmsnorm_quant_kernel(const float* __restrict__ x, const float* __restrict__ w,
                                     i8* __restrict__ qa, i8* __restrict__ qb,
                                     float* __restrict__ scale, int D) {
    __shared__ float ybuf[DMODEL];
    int row = blockIdx.x;
    const float* xr = x + (size_t)row * D;
    float ss = 0.f;
    for (int i = threadIdx.x; i < D; i += blockDim.x) { float v = xr[i]; ss += v * v; }
    ss = block_reduce_sum(ss);
    float inv = rsqrtf(ss / (float)D + 1e-6f);
    float mx = 0.f;
    for (int i = threadIdx.x; i < D; i += blockDim.x) {
        float v = xr[i] * inv * w[i];
        ybuf[i] = v;
        mx = fmaxf(mx, fabsf(v));
    }
    mx = block_reduce_max(mx);
    float S = fmaxf(mx, 1e-30f);
    if (threadIdx.x == 0) scale[row] = S;
    float qs = QMAXF / S;
    for (int i = threadIdx.x; i < D; i += blockDim.x)
        quant2(ybuf[i], qs, &qa[(size_t)row * D + i], &qb[(size_t)row * D + i]);
}

// ---------------- gated rmsnorm + quantize ----------------
__global__ void gated_norm_quant_kernel(const float* __restrict__ proj, const float* __restrict__ scan_y,
                                        const float* __restrict__ w,
                                        i8* __restrict__ qa, i8* __restrict__ qb,
                                        float* __restrict__ scale) {
    __shared__ float buf[DINNER];
    int row = blockIdx.x;
    const float* prow = proj + (size_t)row * PROJ_OUT;
    const float* sy = scan_y + (size_t)row * DINNER;
    float ss = 0.f;
    for (int i = threadIdx.x; i < DINNER; i += blockDim.x) {
        float t = sy[i] * siluf_(prow[i]);
        buf[i] = t; ss += t * t;
    }
    ss = block_reduce_sum(ss);
    float inv = rsqrtf(ss / (float)DINNER + 1e-6f);
    float mx = 0.f;
    for (int i = threadIdx.x; i < DINNER; i += blockDim.x) {
        float v = buf[i] * inv * w[i];
        buf[i] = v;
        mx = fmaxf(mx, fabsf(v));
    }
    mx = block_reduce_max(mx);
    float S = fmaxf(mx, 1e-30f);
    if (threadIdx.x == 0) scale[row] = S;
    float qs = QMAXF / S;
    for (int i = threadIdx.x; i < DINNER; i += blockDim.x)
        quant2(buf[i], qs, &qa[(size_t)row * DINNER + i], &qb[(size_t)row * DINNER + i]);
}

// ---------------- quantize fp32 rows (ff activation) ----------------
__global__ void quant_rows_kernel(const float* __restrict__ src, i8* __restrict__ qa,
                                  i8* __restrict__ qb, float* __restrict__ scale, int D) {
    int row = blockIdx.x;
    const float* sr = src + (size_t)row * D;
    float mx = 0.f;
    for (int i = threadIdx.x; i < D; i += blockDim.x) mx = fmaxf(mx, fabsf(sr[i]));
    mx = block_reduce_max(mx);
    float S = fmaxf(mx, 1e-30f);
    if (threadIdx.x == 0) scale[row] = S;
    float qs = QMAXF / S;
    for (int i = threadIdx.x; i < D; i += blockDim.x)
        quant2(sr[i], qs, &qa[(size_t)row * D + i], &qb[(size_t)row * D + i]);
}

// ---------------- fused conv+silu / params / bcpack ----------------
__global__ void prep_kernel(const float* __restrict__ proj, const float* __restrict__ conv_w,
                            const float* __restrict__ conv_b, float* __restrict__ value,
                            float* __restrict__ par, float* __restrict__ bcT) {
    int bt = blockIdx.x;
    int t = bt & (TQ - 1);
    int tid = threadIdx.x;
    const float* prow = proj + (size_t)bt * PROJ_OUT;
    #pragma unroll
    for (int i = 0; i < 8; ++i) {
        int c = tid + i * 256;
        float acc = conv_b[c];
        #pragma unroll
        for (int k = 0; k < DCONV; ++k) {
            int ts = t - (DCONV - 1) + k;
            if (ts >= 0)
                acc += prow[(ts - t) * (ptrdiff_t)PROJ_OUT + DINNER + c] * conv_w[c * DCONV + k];
        }
        value[(size_t)bt * DINNER + c] = siluf_(acc);
    }
    if (tid < 32) {
        int h = tid;
        par[((size_t)bt * NHEADS + h) * 2 + 0] = softplusf_(prow[PARAM_OFF + 2 * h]);
        par[((size_t)bt * NHEADS + h) * 2 + 1] = sigmoidf_(prow[PARAM_OFF + 2 * h + 1]);
    } else if (tid >= 64 && tid < 80) {
        int n = tid - 64;
        float4 v;
        v.x = prow[BC_OFF + n];
        v.y = prow[BC_OFF + 16 + n];
        v.z = prow[BC_OFF + 32 + n];
        v.w = prow[BC_OFF + 48 + n];
        ((float4*)bcT)[(size_t)bt * 16 + n] = v;
    }
}

// ---------------- sequential SSM scan ----------------
__global__ void scan_kernel(const float* __restrict__ bcT, const float* __restrict__ par,
                            const float* __restrict__ value, float* __restrict__ scan_y) {
    int blk = blockIdx.x;
    int bh = blk >> 1;
    int b = bh >> 5;
    int h = bh & 31;
    int half = blk & 1;
    int tid = threadIdx.x;
    int p = half * 32 + (tid >> 4);
    int n = tid & 15;
    float S0 = 0.f, S1 = 0.f;
    const size_t rowbase = (size_t)b * TQ;
    const float4* bc4 = (const float4*)bcT;
    const float2* ad2 = (const float2*)par;
    float4 nbc = bc4[rowbase * 16 + n];
    float2 nad = ad2[rowbase * NHEADS + h];
    float  nu  = value[rowbase * DINNER + h * DHEAD + p];
    for (int t = 0; t < TQ; ++t) {
        float4 bcv = nbc; float2 ad = nad; float u = nu;
        if (t + 1 < TQ) {
            size_t r2 = rowbase + t + 1;
            nbc = bc4[r2 * 16 + n];
            nad = ad2[r2 * NHEADS + h];
            nu  = value[r2 * DINNER + h * DHEAD + p];
        }
        float A = ad.x, dt = ad.y;
        float dtA = dt * A;
        float du = dt * u;
        float s0n = fmaf(-dtA, S1, fmaf(bcv.x, du, S0));
        float s1n = fmaf(dt, S0, fmaf(1.f - dt * dtA, S1, dt * bcv.y * du));
        S0 = s0n; S1 = s1n;
        float y = bcv.z * s0n + bcv.w * s1n;
        y += __shfl_xor_sync(0xffffffffu, y, 8);
        y += __shfl_xor_sync(0xffffffffu, y, 4);
        y += __shfl_xor_sync(0xffffffffu, y, 2);
        y += __shfl_xor_sync(0xffffffffu, y, 1);
        if (n == 0) scan_y[(rowbase + t) * DINNER + h * DHEAD + p] = y;
    }
}

// ---------------- int8 split-precision GEMM via mma.sync.m16n8k32 ----------------
// C[M,N] = A @ W^T with A ~ (sA/32512)(256 Aa + Ab), W ~ (sW/32512)(256 Wa + Wb).
// acc1 = sum Aa*Wa ; acc2 = sum (Aa*Wb + Ab*Wa) ; C = sA*sW*SCF*(256*acc1 + acc2).
// CTA 128x128, BK=64 int8, 8 warps (32x64 each), 3-stage cp.async, 1 sync/chunk.
// mode 0: C = v ; 1: v + bias? + res? ; 2: C = gelu(v + bias) (fp32 out)
#define TIL 10240                   // 128 rows x 80B
#define STG (4 * TIL)               // 40960
#define NST 3
#define GEMM_SMEM (NST * STG)       // 122880
__global__ void __launch_bounds__(256, 1)
gemm_i8(const i8* __restrict__ Aa, const i8* __restrict__ Ab,
        const i8* __restrict__ Wa, const i8* __restrict__ Wb,
        const float* __restrict__ sA, const float* __restrict__ sW,
        const float* __restrict__ bias, const float* __restrict__ res,
        float* __restrict__ C, int N, int K, int mode) {
    extern __shared__ __align__(16) i8 dsm[];
    const uint32_t s0 = smem_u32(dsm);
    const int tid = threadIdx.x, wid = tid >> 5, lane = tid & 31;
    const int row0 = blockIdx.y * 128, col0 = blockIdx.x * 128;
    const int wm = wid & 3, wn = wid >> 2;          // 4 x 2 warp grid: 32(M) x 64(N)
    const int nch = K >> 6;

    int acc1[2][8][4], acc2[2][8][4];
    #pragma unroll
    for (int mt = 0; mt < 2; ++mt)
        #pragma unroll
        for (int nt = 0; nt < 8; ++nt)
            #pragma unroll
            for (int q = 0; q < 4; ++q) { acc1[mt][nt][q] = 0; acc2[mt][nt][q] = 0; }

    // loader: per tile 512 16B-chunks; thread covers rows lr, lr+64 at 16B-col lc
    const int lr = tid >> 2, lc = tid & 3;
    const uint32_t dst = lr * 80 + lc * 16;
    const i8* pAa = Aa + (size_t)(row0 + lr) * K + lc * 16;
    const i8* pAb = Ab + (size_t)(row0 + lr) * K + lc * 16;
    const i8* pWa = Wa + (size_t)(col0 + lr) * K + lc * 16;
    const i8* pWb = Wb + (size_t)(col0 + lr) * K + lc * 16;

    #define LOADC(stg, k0) do {                                              \
        uint32_t _b = s0 + (stg) * STG + dst;                                \
        CP_ASYNC16(_b,                     pAa + (k0));                      \
        CP_ASYNC16(_b + 64 * 80,           pAa + (size_t)64 * K + (k0));     \
        CP_ASYNC16(_b + TIL,               pAb + (k0));                      \
        CP_ASYNC16(_b + TIL + 64 * 80,     pAb + (size_t)64 * K + (k0));     \
        CP_ASYNC16(_b + 2 * TIL,           pWa + (k0));                      \
        CP_ASYNC16(_b + 2 * TIL + 64 * 80, pWa + (size_t)64 * K + (k0));     \
        CP_ASYNC16(_b + 3 * TIL,           pWb + (k0));                      \
        CP_ASYNC16(_b + 3 * TIL + 64 * 80, pWb + (size_t)64 * K + (k0));     \
        CP_COMMIT();                                                         \
    } while (0)

    LOADC(0, 0);
    LOADC(1, 64);

    // ldmatrix addresses (b16 view: 2 int8 per unit; row stride 80B)
    const uint32_t a_row = (uint32_t)(wm * 32 + (lane & 15));
    const uint32_t a_coff = (uint32_t)((lane >> 4) * 8);       // b16 units
    const uint32_t b_row = (uint32_t)(wn * 64 + (lane & 7));
    const uint32_t b_coff = (uint32_t)(((lane >> 3) & 1) * 8); // b16 units

    for (int ch = 0; ch < nch; ++ch) {
        if (ch + 1 < nch)
            asm volatile("cp.async.wait_group 1;" ::: "memory");
        else
            asm volatile("cp.async.wait_group 0;" ::: "memory");
        __syncthreads();
        if (ch + 2 < nch)
            LOADC((ch + 2) % NST, (ch + 2) << 6);

        const uint32_t sb = s0 + (ch % NST) * STG;
        const uint32_t sAa_ = sb, sAb_ = sb + TIL, sWa_ = sb + 2 * TIL, sWb_ = sb + 3 * TIL;
        #pragma unroll
        for (int ks = 0; ks < 2; ++ks) {
            const uint32_t acol = (ks * 16 + a_coff) * 2;      // bytes
            const uint32_t bcol = (ks * 16 + b_coff) * 2;
            uint32_t aa[2][4], ab[2][4], wa[8][2], wb[8][2];
            #pragma unroll
            for (int mt = 0; mt < 2; ++mt) {
                ldsm_x4(aa[mt], sAa_ + (a_row + mt * 16) * 80 + acol);
                ldsm_x4(ab[mt], sAb_ + (a_row + mt * 16) * 80 + acol);
            }
            #pragma unroll
            for (int nt = 0; nt < 8; ++nt) {
                ldsm_x2(wa[nt], sWa_ + (b_row + nt * 8) * 80 + bcol);
                ldsm_x2(wb[nt], sWb_ + (b_row + nt * 8) * 80 + bcol);
            }
            #pragma unroll
            for (int mt = 0; mt < 2; ++mt)
                #pragma unroll
                for (int nt = 0; nt < 8; ++nt) {
                    mma_s8(acc1[mt][nt], aa[mt], wa[nt]);
                    mma_s8(acc2[mt][nt], aa[mt], wb[nt]);
                    mma_s8(acc2[mt][nt], ab[mt], wa[nt]);
                }
        }
    }

    // epilogue
    const int er = lane >> 2, ec = (lane & 3) << 1;
    float srow[2][2];
    #pragma unroll
    for (int mt = 0; mt < 2; ++mt)
        #pragma unroll
        for (int half = 0; half < 2; ++half)
            srow[mt][half] = sA[row0 + wm * 32 + mt * 16 + er + half * 8] * SCF;
    #pragma unroll
    for (int mt = 0; mt < 2; ++mt) {
        #pragma unroll
        for (int nt = 0; nt < 8; ++nt) {
            int gc = col0 + wn * 64 + nt * 8 + ec;
            float t0 = sW[gc], t1 = sW[gc + 1];
            #pragma unroll
            for (int half = 0; half < 2; ++half) {
                int r = row0 + wm * 32 + mt * 16 + er + half * 8;
                float f0 = fmaf(256.f, (float)acc1[mt][nt][half * 2 + 0], (float)acc2[mt][nt][half * 2 + 0]);
                float f1 = fmaf(256.f, (float)acc1[mt][nt][half * 2 + 1], (float)acc2[mt][nt][half * 2 + 1]);
                float v0 = f0 * srow[mt][half] * t0;
                float v1 = f1 * srow[mt][half] * t1;
                if (mode == 2) {
                    v0 = geluf_(v0 + bias[gc]);
                    v1 = geluf_(v1 + bias[gc + 1]);
                } else {
                    if (bias) { v0 += bias[gc]; v1 += bias[gc + 1]; }
                    if (res) {
                        const float* rp = res + (size_t)r * N + gc;
                        v0 += rp[0]; v1 += rp[1];
                    }
                }
                float2 v; v.x = v0; v.y = v1;
                *(float2*)(C + (size_t)r * N + gc) = v;
            }
        }
    }
}

// ---------------- launch ----------------
extern "C" void kernel_launch(void* const* d_in, const int* in_sizes, int n_in,
                              void* d_out, int out_size) {
    const float* x       = (const float*)d_in[0];
    const float* w_in    = (const float*)d_in[1];
    const float* conv_w  = (const float*)d_in[2];
    const float* conv_b  = (const float*)d_in[3];
    const float* norm1_w = (const float*)d_in[4];
    const float* out_nw  = (const float*)d_in[5];
    const float* w_out   = (const float*)d_in[6];
    const float* norm2_w = (const float*)d_in[7];
    const float* ff_w1   = (const float*)d_in[8];
    const float* ff_b1   = (const float*)d_in[9];
    const float* ff_w2   = (const float*)d_in[10];
    const float* ff_b2   = (const float*)d_in[11];
    float* out = (float*)d_out;

    float *proj, *val, *par, *bcT, *scan, *x1, *ff;
    i8 *xa, *xb, *ga, *gb, *ha, *hb, *fa, *fb;
    i8 *wina, *winb, *woa, *wob, *w1a, *w1b, *w2a, *w2b;
    float *sx, *sg, *sh, *sf, *twin, *two, *tw1, *tw2;
    cudaGetSymbolAddress((void**)&proj, g_proj);
    cudaGetSymbolAddress((void**)&val,  g_val);
    cudaGetSymbolAddress((void**)&par,  g_par);
    cudaGetSymbolAddress((void**)&bcT,  g_bcT);
    cudaGetSymbolAddress((void**)&scan, g_scan);
    cudaGetSymbolAddress((void**)&x1,   g_x1);
    cudaGetSymbolAddress((void**)&ff,   g_ff);
    cudaGetSymbolAddress((void**)&xa, g_xa); cudaGetSymbolAddress((void**)&xb, g_xb);
    cudaGetSymbolAddress((void**)&ga, g_ga); cudaGetSymbolAddress((void**)&gb, g_gb);
    cudaGetSymbolAddress((void**)&ha, g_ha); cudaGetSymbolAddress((void**)&hb, g_hb);
    cudaGetSymbolAddress((void**)&fa, g_fa); cudaGetSymbolAddress((void**)&fb, g_fb);
    cudaGetSymbolAddress((void**)&wina, g_wina); cudaGetSymbolAddress((void**)&winb, g_winb);
    cudaGetSymbolAddress((void**)&woa,  g_woa);  cudaGetSymbolAddress((void**)&wob,  g_wob);
    cudaGetSymbolAddress((void**)&w1a,  g_w1a);  cudaGetSymbolAddress((void**)&w1b,  g_w1b);
    cudaGetSymbolAddress((void**)&w2a,  g_w2a);  cudaGetSymbolAddress((void**)&w2b,  g_w2b);
    cudaGetSymbolAddress((void**)&sx, g_sx); cudaGetSymbolAddress((void**)&sg, g_sg);
    cudaGetSymbolAddress((void**)&sh, g_sh); cudaGetSymbolAddress((void**)&sf, g_sf);
    cudaGetSymbolAddress((void**)&twin, g_twin); cudaGetSymbolAddress((void**)&two, g_two);
    cudaGetSymbolAddress((void**)&tw1, g_tw1);   cudaGetSymbolAddress((void**)&tw2, g_tw2);

    cudaFuncSetAttribute(gemm_i8, cudaFuncAttributeMaxDynamicSharedMemorySize, GEMM_SMEM);

    // weight quantization (idempotent)
    quant_w_kernel<<<PROJ_OUT, 256>>>(w_in, wina, winb, twin, DMODEL);
    quant_w_kernel<<<DMODEL, 256>>>(w_out, woa, wob, two, DINNER);
    quant_w_kernel<<<DFF, 256>>>(ff_w1, w1a, w1b, tw1, DMODEL);
    quant_w_kernel<<<DMODEL, 256>>>(ff_w2, w2a, w2b, tw2, DFF);

    // 1. h1 = rmsnorm(x), quantize
    rmsnorm_quant_kernel<<<BT, 256>>>(x, norm1_w, xa, xb, sx, DMODEL);
    // 2. proj = h1 @ w_in^T  (4096 x 4224 x 1024)
    gemm_i8<<<dim3(PROJ_OUT / 128, BT / 128), 256, GEMM_SMEM>>>(
        xa, xb, wina, winb, sx, twin, nullptr, nullptr, proj, PROJ_OUT, DMODEL, 0);
    // 3. conv+silu / params / bcpack
    prep_kernel<<<BT, 256>>>(proj, conv_w, conv_b, val, par, bcT);
    // 4. scan
    scan_kernel<<<2 * BQ * NHEADS, 512>>>(bcT, par, val, scan);
    // 5. yg = rmsnorm(scan * silu(gate)), quantize
    gated_norm_quant_kernel<<<BT, 256>>>(proj, scan, out_nw, ga, gb, sg);
    // 6. x1 = x + yg @ w_out^T  (4096 x 1024 x 2048)
    gemm_i8<<<dim3(DMODEL / 128, BT / 128), 256, GEMM_SMEM>>>(
        ga, gb, woa, wob, sg, two, nullptr, x, x1, DMODEL, DINNER, 1);
    // 7. h2 = rmsnorm(x1), quantize
    rmsnorm_quant_kernel<<<BT, 256>>>(x1, norm2_w, ha, hb, sh, DMODEL);
    // 8. ff = gelu(h2 @ ff_w1^T + b1)  (fp32)
    gemm_i8<<<dim3(DFF / 128, BT / 128), 256, GEMM_SMEM>>>(
        ha, hb, w1a, w1b, sh, tw1, ff_b1, nullptr, ff, DFF, DMODEL, 2);
    // 9. quantize ff rows
    quant_rows_kernel<<<BT, 256>>>(ff, fa, fb, sf, DFF);
    // 10. out = x1 + ffq @ ff_w2^T + b2  (4096 x 1024 x 4096)
    gemm_i8<<<dim3(DMODEL / 128, BT / 128), 256, GEMM_SMEM>>>(
        fa, fb, w2a, w2b, sf, tw2, ff_b2, x1, out, DMODEL, DFF, 1);
}

// round 10
// speedup vs baseline: 2.2066x; 2.2066x over previous
#include <cuda_runtime.h>
#include <cuda_bf16.h>
#include <math.h>
#include <stdint.h>

typedef __nv_bfloat16 bf16;

#define BQ 2
#define TQ 2048
#define DMODEL 1024
#define DINNER 2048
#define NHEADS 32
#define DHEAD 64
#define DCONV 4
#define PROJ_OUT 4224
#define BT 4096
#define PARAM_OFF 4096
#define BC_OFF 4160
#define DFF 4096

// ---------------- scratch (device globals; no allocation) ----------------
__device__ float g_proj[(size_t)BT * PROJ_OUT];
__device__ float g_val [(size_t)BT * DINNER];
__device__ float g_par [(size_t)BT * NHEADS * 2];
__device__ float g_bcT [(size_t)BT * 64];
__device__ float g_scan[(size_t)BT * DINNER];
__device__ float g_x1  [BT * DMODEL];
__device__ bf16 g_h1h[BT * DMODEL],         g_h1l[BT * DMODEL];
__device__ bf16 g_ygh[(size_t)BT * DINNER], g_ygl[(size_t)BT * DINNER];
__device__ bf16 g_h2h[BT * DMODEL],         g_h2l[BT * DMODEL];
__device__ bf16 g_ffh[(size_t)BT * DFF],    g_ffl[(size_t)BT * DFF];
__device__ bf16 g_winh[PROJ_OUT * 1024],    g_winl[PROJ_OUT * 1024];
__device__ bf16 g_woh [1024 * 2048],        g_wol [1024 * 2048];
__device__ bf16 g_w1h [4096 * 1024],        g_w1l [4096 * 1024];
__device__ bf16 g_w2h [1024 * 4096],        g_w2l [1024 * 4096];

// ---------------- math helpers ----------------
__device__ __forceinline__ float sigmoidf_(float x) { return 1.f / (1.f + __expf(-x)); }
__device__ __forceinline__ float siluf_(float x)    { return x / (1.f + __expf(-x)); }
__device__ __forceinline__ float geluf_(float x) {
    float x3 = x * x * x;
    return 0.5f * x * (1.f + tanhf(0.7978845608028654f * (x + 0.044715f * x3)));
}
__device__ __forceinline__ float softplusf_(float x) {
    return (x > 20.f) ? x : log1pf(expf(x));
}
__device__ __forceinline__ void split1(float v, bf16* h, bf16* l) {
    bf16 hh = __float2bfloat16(v);
    *h = hh;
    *l = __float2bfloat16(v - __bfloat162float(hh));
}

__device__ __forceinline__ float block_reduce_sum(float v) {
    __shared__ float sh[32];
    int lane = threadIdx.x & 31, wid = threadIdx.x >> 5;
    int nwarps = blockDim.x >> 5;
    #pragma unroll
    for (int m = 16; m > 0; m >>= 1) v += __shfl_xor_sync(0xffffffffu, v, m);
    if (lane == 0) sh[wid] = v;
    __syncthreads();
    if (wid == 0) {
        v = (lane < nwarps) ? sh[lane] : 0.f;
        #pragma unroll
        for (int m = 16; m > 0; m >>= 1) v += __shfl_xor_sync(0xffffffffu, v, m);
        if (lane == 0) sh[0] = v;
    }
    __syncthreads();
    return sh[0];
}

// ---------------- low-level (sm_80-compatible only) ----------------
__device__ __forceinline__ uint32_t smem_u32(const void* p) {
    uint32_t a;
    asm("{ .reg .u64 t; cvta.to.shared.u64 t, %1; cvt.u32.u64 %0, t; }" : "=r"(a) : "l"(p));
    return a;
}
#define CP_ASYNC16(dst, src) \
    asm volatile("cp.async.cg.shared.global [%0], [%1], 16;" :: "r"((uint32_t)(dst)), "l"(src))
#define CP_COMMIT() asm volatile("cp.async.commit_group;" ::: "memory")

__device__ __forceinline__ void ldsm_x4(uint32_t* r, uint32_t addr) {
    asm volatile("ldmatrix.sync.aligned.m8n8.x4.shared.b16 {%0,%1,%2,%3}, [%4];"
                 : "=r"(r[0]), "=r"(r[1]), "=r"(r[2]), "=r"(r[3]) : "r"(addr));
}
__device__ __forceinline__ void ldsm_x2(uint32_t* r, uint32_t addr) {
    asm volatile("ldmatrix.sync.aligned.m8n8.x2.shared.b16 {%0,%1}, [%2];"
                 : "=r"(r[0]), "=r"(r[1]) : "r"(addr));
}
__device__ __forceinline__ void mma16816(float* c, const uint32_t* a, const uint32_t* b) {
    asm volatile("mma.sync.aligned.m16n8k16.row.col.f32.bf16.bf16.f32 "
                 "{%0,%1,%2,%3}, {%4,%5,%6,%7}, {%8,%9}, {%0,%1,%2,%3};"
                 : "+f"(c[0]), "+f"(c[1]), "+f"(c[2]), "+f"(c[3])
                 : "r"(a[0]), "r"(a[1]), "r"(a[2]), "r"(a[3]), "r"(b[0]), "r"(b[1]));
}

// ---------------- rmsnorm + bf16 split (vectorized, D=1024, 256 thr) ----------------
__global__ void rmsnorm_split_kernel(const float* __restrict__ x, const float* __restrict__ w,
                                     bf16* __restrict__ oh, bf16* __restrict__ ol) {
    int row = blockIdx.x;
    int i = threadIdx.x;
    const float4* xr = (const float4*)(x + (size_t)row * DMODEL);
    float4 v = xr[i];
    float ss = v.x * v.x + v.y * v.y + v.z * v.z + v.w * v.w;
    ss = block_reduce_sum(ss);
    float inv = rsqrtf(ss / (float)DMODEL + 1e-6f);
    float4 wv = ((const float4*)w)[i];
    float o0 = v.x * inv * wv.x, o1 = v.y * inv * wv.y;
    float o2 = v.z * inv * wv.z, o3 = v.w * inv * wv.w;
    __nv_bfloat162 h0, h1, l0, l1;
    split1(o0, &h0.x, &l0.x); split1(o1, &h0.y, &l0.y);
    split1(o2, &h1.x, &l1.x); split1(o3, &h1.y, &l1.y);
    __nv_bfloat162* ohp = (__nv_bfloat162*)(oh + (size_t)row * DMODEL);
    __nv_bfloat162* olp = (__nv_bfloat162*)(ol + (size_t)row * DMODEL);
    ohp[2 * i] = h0; ohp[2 * i + 1] = h1;
    olp[2 * i] = l0; olp[2 * i + 1] = l1;
}

// ---------------- gated rmsnorm + split (vectorized, DINNER=2048) ----------------
__global__ void gated_norm_split_kernel(const float* __restrict__ proj, const float* __restrict__ scan_y,
                                        const float* __restrict__ w,
                                        bf16* __restrict__ oh, bf16* __restrict__ ol) {
    int row = blockIdx.x;
    int tid = threadIdx.x;
    const float4* prow = (const float4*)(proj + (size_t)row * PROJ_OUT);
    const float4* sy = (const float4*)(scan_y + (size_t)row * DINNER);
    float4 tv[2];
    float ss = 0.f;
    #pragma unroll
    for (int q = 0; q < 2; ++q) {
        int i = tid + q * 256;
        float4 g = prow[i];
        float4 s = sy[i];
        float4 t;
        t.x = s.x * siluf_(g.x); t.y = s.y * siluf_(g.y);
        t.z = s.z * siluf_(g.z); t.w = s.w * siluf_(g.w);
        tv[q] = t;
        ss += t.x * t.x + t.y * t.y + t.z * t.z + t.w * t.w;
    }
    ss = block_reduce_sum(ss);
    float inv = rsqrtf(ss / (float)DINNER + 1e-6f);
    __nv_bfloat162* ohp = (__nv_bfloat162*)(oh + (size_t)row * DINNER);
    __nv_bfloat162* olp = (__nv_bfloat162*)(ol + (size_t)row * DINNER);
    #pragma unroll
    for (int q = 0; q < 2; ++q) {
        int i = tid + q * 256;
        float4 wv = ((const float4*)w)[i];
        float o0 = tv[q].x * inv * wv.x, o1 = tv[q].y * inv * wv.y;
        float o2 = tv[q].z * inv * wv.z, o3 = tv[q].w * inv * wv.w;
        __nv_bfloat162 h0, h1, l0, l1;
        split1(o0, &h0.x, &l0.x); split1(o1, &h0.y, &l0.y);
        split1(o2, &h1.x, &l1.x); split1(o3, &h1.y, &l1.y);
        ohp[2 * i] = h0; ohp[2 * i + 1] = h1;
        olp[2 * i] = l0; olp[2 * i + 1] = l1;
    }
}

// ---------------- fp32 -> bf16 hi/lo split (vectorized, n % 4 == 0) ----------------
__global__ void split4_kernel(const float4* __restrict__ src, __nv_bfloat162* __restrict__ hi,
                              __nv_bfloat162* __restrict__ lo, int n4) {
    int i = blockIdx.x * blockDim.x + threadIdx.x;
    if (i >= n4) return;
    float4 v = src[i];
    __nv_bfloat162 h0, h1, l0, l1;
    split1(v.x, &h0.x, &l0.x); split1(v.y, &h0.y, &l0.y);
    split1(v.z, &h1.x, &l1.x); split1(v.w, &h1.y, &l1.y);
    hi[2 * i] = h0; hi[2 * i + 1] = h1;
    lo[2 * i] = l0; lo[2 * i + 1] = l1;
}

// ---------------- fused conv+silu / params / bcpack (one block per (b,t)) ----------------
__global__ void prep_kernel(const float* __restrict__ proj, const float* __restrict__ conv_w,
                            const float* __restrict__ conv_b, float* __restrict__ value,
                            float* __restrict__ par, float* __restrict__ bcT) {
    int bt = blockIdx.x;
    int t = bt & (TQ - 1);
    int tid = threadIdx.x;
    const float* prow = proj + (size_t)bt * PROJ_OUT;
    #pragma unroll
    for (int i = 0; i < 8; ++i) {
        int c = tid + i * 256;
        float acc = conv_b[c];
        #pragma unroll
        for (int k = 0; k < DCONV; ++k) {
            int ts = t - (DCONV - 1) + k;
            if (ts >= 0)
                acc += prow[(ts - t) * (ptrdiff_t)PROJ_OUT + DINNER + c] * conv_w[c * DCONV + k];
        }
        value[(size_t)bt * DINNER + c] = siluf_(acc);
    }
    if (tid < 32) {
        int h = tid;
        par[((size_t)bt * NHEADS + h) * 2 + 0] = softplusf_(prow[PARAM_OFF + 2 * h]);
        par[((size_t)bt * NHEADS + h) * 2 + 1] = sigmoidf_(prow[PARAM_OFF + 2 * h + 1]);
    } else if (tid >= 64 && tid < 80) {
        int n = tid - 64;
        float4 v;
        v.x = prow[BC_OFF + n];
        v.y = prow[BC_OFF + 16 + n];
        v.z = prow[BC_OFF + 32 + n];
        v.w = prow[BC_OFF + 48 + n];
        ((float4*)bcT)[(size_t)bt * 16 + n] = v;
    }
}

// ---------------- sequential SSM scan ----------------
__global__ void scan_kernel(const float* __restrict__ bcT, const float* __restrict__ par,
                            const float* __restrict__ value, float* __restrict__ scan_y) {
    int blk = blockIdx.x;
    int bh = blk >> 1;
    int b = bh >> 5;
    int h = bh & 31;
    int half = blk & 1;
    int tid = threadIdx.x;
    int p = half * 32 + (tid >> 4);
    int n = tid & 15;
    float S0 = 0.f, S1 = 0.f;
    const size_t rowbase = (size_t)b * TQ;
    const float4* bc4 = (const float4*)bcT;
    const float2* ad2 = (const float2*)par;
    float4 nbc = bc4[rowbase * 16 + n];
    float2 nad = ad2[rowbase * NHEADS + h];
    float  nu  = value[rowbase * DINNER + h * DHEAD + p];
    for (int t = 0; t < TQ; ++t) {
        float4 bcv = nbc; float2 ad = nad; float u = nu;
        if (t + 1 < TQ) {
            size_t r2 = rowbase + t + 1;
            nbc = bc4[r2 * 16 + n];
            nad = ad2[r2 * NHEADS + h];
            nu  = value[r2 * DINNER + h * DHEAD + p];
        }
        float A = ad.x, dt = ad.y;
        float dtA = dt * A;
        float du = dt * u;
        float s0n = fmaf(-dtA, S1, fmaf(bcv.x, du, S0));
        float s1n = fmaf(dt, S0, fmaf(1.f - dt * dtA, S1, dt * bcv.y * du));
        S0 = s0n; S1 = s1n;
        float y = bcv.z * s0n + bcv.w * s1n;
        y += __shfl_xor_sync(0xffffffffu, y, 8);
        y += __shfl_xor_sync(0xffffffffu, y, 4);
        y += __shfl_xor_sync(0xffffffffu, y, 2);
        y += __shfl_xor_sync(0xffffffffu, y, 1);
        if (n == 0) scan_y[(rowbase + t) * DINNER + h * DHEAD + p] = y;
    }
}

// ---------------- bf16 split-precision GEMM via mma.sync (HMMA) — R6 config ----------------
// CTA 128x128, BK=32, 256 threads (8 warps, 64x32 each), 2-stage cp.async.
// Products Ah*Bh + Ah*Bl + Al*Bh interleaved per chunk.
// mode 0: C = acc ; 1: + bias?/res? ; 2: split(gelu(acc+bias)) -> Oh/Ol
#define ASTRIDE 40                  // bf16 per smem row (80B) -> conflict-free ldmatrix
#define TILEB (128 * ASTRIDE * 2)   // bytes per tile (10240)
#define STAGEB (4 * TILEB)          // bytes per stage (40960)
#define GEMM_SMEM (2 * STAGEB)      // 81920
__global__ void __launch_bounds__(256, 2)
gemm_mma(const bf16* __restrict__ Ah, const bf16* __restrict__ Al,
         const bf16* __restrict__ Bh, const bf16* __restrict__ Bl,
         const float* __restrict__ bias, const float* __restrict__ res,
         float* __restrict__ C, bf16* __restrict__ Oh, bf16* __restrict__ Ol,
         int N, int K, int mode) {
    extern __shared__ __align__(16) bf16 dsm[];
    const uint32_t s0 = smem_u32(dsm);
    const int tid = threadIdx.x, wid = tid >> 5, lane = tid & 31;
    const int row0 = blockIdx.y * 128, col0 = blockIdx.x * 128;
    const int wm = wid & 1, wn = wid >> 1;          // 2 x 4 warp grid
    const int nch = K >> 5;

    float acc[4][4][4];
    #pragma unroll
    for (int mt = 0; mt < 4; ++mt)
        #pragma unroll
        for (int nt = 0; nt < 4; ++nt)
            #pragma unroll
            for (int q = 0; q < 4; ++q) acc[mt][nt][q] = 0.f;

    const int lr = tid >> 2, lc = tid & 3;
    const bf16* gAh = Ah + (size_t)(row0 + lr) * K + lc * 8;
    const bf16* gAl = Al + (size_t)(row0 + lr) * K + lc * 8;
    const bf16* gBh = Bh + (size_t)(col0 + lr) * K + lc * 8;
    const bf16* gBl = Bl + (size_t)(col0 + lr) * K + lc * 8;
    const uint32_t dst = lr * 80 + lc * 16;

    #define LOAD_CHUNK(stg, k0) do {                                                   \
        uint32_t _b = s0 + (stg) * STAGEB + dst;                                       \
        CP_ASYNC16(_b,                     gAh + (k0));                                \
        CP_ASYNC16(_b + 64 * 80,           gAh + (size_t)64 * K + (k0));               \
        CP_ASYNC16(_b + TILEB,             gAl + (k0));                                \
        CP_ASYNC16(_b + TILEB + 64 * 80,   gAl + (size_t)64 * K + (k0));               \
        CP_ASYNC16(_b + 2 * TILEB,           gBh + (k0));                              \
        CP_ASYNC16(_b + 2 * TILEB + 64 * 80, gBh + (size_t)64 * K + (k0));             \
        CP_ASYNC16(_b + 3 * TILEB,           gBl + (k0));                              \
        CP_ASYNC16(_b + 3 * TILEB + 64 * 80, gBl + (size_t)64 * K + (k0));             \
        CP_COMMIT();                                                                   \
    } while (0)

    LOAD_CHUNK(0, 0);

    const uint32_t a_row = (uint32_t)(wm * 64 + (lane & 15));
    const uint32_t a_coff = (uint32_t)((lane >> 4) * 8);
    const uint32_t b_row = (uint32_t)(wn * 32 + (lane & 7));
    const uint32_t b_coff = (uint32_t)(((lane >> 3) & 1) * 8);

    for (int ch = 0; ch < nch; ++ch) {
        const int stg = ch & 1;
        if (ch + 1 < nch) {
            LOAD_CHUNK(stg ^ 1, (ch + 1) << 5);
            asm volatile("cp.async.wait_group 1;" ::: "memory");
        } else {
            asm volatile("cp.async.wait_group 0;" ::: "memory");
        }
        __syncthreads();

        const uint32_t sb = s0 + stg * STAGEB;
        const uint32_t sAh_ = sb, sAl_ = sb + TILEB, sBh_ = sb + 2 * TILEB, sBl_ = sb + 3 * TILEB;
        #pragma unroll
        for (int ks = 0; ks < 2; ++ks) {
            const uint32_t acol = (ks * 16 + a_coff) * 2;
            const uint32_t bcol = (ks * 16 + b_coff) * 2;
            uint32_t afr[4][4], bh_[4][2], bl_[4][2];
            #pragma unroll
            for (int mt = 0; mt < 4; ++mt)
                ldsm_x4(afr[mt], sAh_ + (a_row + mt * 16) * 80 + acol);
            #pragma unroll
            for (int nt = 0; nt < 4; ++nt) {
                ldsm_x2(bh_[nt], sBh_ + (b_row + nt * 8) * 80 + bcol);
                ldsm_x2(bl_[nt], sBl_ + (b_row + nt * 8) * 80 + bcol);
            }
            #pragma unroll
            for (int mt = 0; mt < 4; ++mt)
                #pragma unroll
                for (int nt = 0; nt < 4; ++nt) {
                    mma16816(acc[mt][nt], afr[mt], bh_[nt]);
                    mma16816(acc[mt][nt], afr[mt], bl_[nt]);
                }
            #pragma unroll
            for (int mt = 0; mt < 4; ++mt)
                ldsm_x4(afr[mt], sAl_ + (a_row + mt * 16) * 80 + acol);   // reuse regs
            #pragma unroll
            for (int mt = 0; mt < 4; ++mt)
                #pragma unroll
                for (int nt = 0; nt < 4; ++nt)
                    mma16816(acc[mt][nt], afr[mt], bh_[nt]);
        }
        __syncthreads();
    }

    // epilogue
    const int er = lane >> 2, ec = (lane & 3) << 1;
    #pragma unroll
    for (int mt = 0; mt < 4; ++mt) {
        #pragma unroll
        for (int nt = 0; nt < 4; ++nt) {
            int gr = row0 + wm * 64 + mt * 16 + er;
            int gc = col0 + wn * 32 + nt * 8 + ec;
            const float* cc = acc[mt][nt];
            #pragma unroll
            for (int half = 0; half < 2; ++half) {
                int r = gr + half * 8;
                float v0 = cc[half * 2 + 0], v1 = cc[half * 2 + 1];
                if (mode == 2) {
                    v0 = geluf_(v0 + bias[gc]);
                    v1 = geluf_(v1 + bias[gc + 1]);
                    __nv_bfloat162 hp, lp;
                    split1(v0, &hp.x, &lp.x);
                    split1(v1, &hp.y, &lp.y);
                    size_t o = (size_t)r * N + gc;
                    *(__nv_bfloat162*)(Oh + o) = hp;
                    *(__nv_bfloat162*)(Ol + o) = lp;
                } else {
                    if (bias) { v0 += bias[gc]; v1 += bias[gc + 1]; }
                    if (res) {
                        const float* rp = res + (size_t)r * N + gc;
                        v0 += rp[0]; v1 += rp[1];
                    }
                    float2 v; v.x = v0; v.y = v1;
                    *(float2*)(C + (size_t)r * N + gc) = v;
                }
            }
        }
    }
}

// ---------------- launch ----------------
extern "C" void kernel_launch(void* const* d_in, const int* in_sizes, int n_in,
                              void* d_out, int out_size) {
    const float* x       = (const float*)d_in[0];
    const float* w_in    = (const float*)d_in[1];
    const float* conv_w  = (const float*)d_in[2];
    const float* conv_b  = (const float*)d_in[3];
    const float* norm1_w = (const float*)d_in[4];
    const float* out_nw  = (const float*)d_in[5];
    const float* w_out   = (const float*)d_in[6];
    const float* norm2_w = (const float*)d_in[7];
    const float* ff_w1   = (const float*)d_in[8];
    const float* ff_b1   = (const float*)d_in[9];
    const float* ff_w2   = (const float*)d_in[10];
    const float* ff_b2   = (const float*)d_in[11];
    float* out = (float*)d_out;

    float *proj, *val, *par, *bcT, *scan, *x1;
    bf16 *h1h, *h1l, *ygh, *ygl, *h2h, *h2l, *ffh, *ffl;
    bf16 *winh, *winl, *woh, *wol, *w1h, *w1l, *w2h, *w2l;
    cudaGetSymbolAddress((void**)&proj, g_proj);
    cudaGetSymbolAddress((void**)&val,  g_val);
    cudaGetSymbolAddress((void**)&par,  g_par);
    cudaGetSymbolAddress((void**)&bcT,  g_bcT);
    cudaGetSymbolAddress((void**)&scan, g_scan);
    cudaGetSymbolAddress((void**)&x1,   g_x1);
    cudaGetSymbolAddress((void**)&h1h,  g_h1h);  cudaGetSymbolAddress((void**)&h1l, g_h1l);
    cudaGetSymbolAddress((void**)&ygh,  g_ygh);  cudaGetSymbolAddress((void**)&ygl, g_ygl);
    cudaGetSymbolAddress((void**)&h2h,  g_h2h);  cudaGetSymbolAddress((void**)&h2l, g_h2l);
    cudaGetSymbolAddress((void**)&ffh,  g_ffh);  cudaGetSymbolAddress((void**)&ffl, g_ffl);
    cudaGetSymbolAddress((void**)&winh, g_winh); cudaGetSymbolAddress((void**)&winl, g_winl);
    cudaGetSymbolAddress((void**)&woh,  g_woh);  cudaGetSymbolAddress((void**)&wol, g_wol);
    cudaGetSymbolAddress((void**)&w1h,  g_w1h);  cudaGetSymbolAddress((void**)&w1l, g_w1l);
    cudaGetSymbolAddress((void**)&w2h,  g_w2h);  cudaGetSymbolAddress((void**)&w2l, g_w2l);

    cudaFuncSetAttribute(gemm_mma, cudaFuncAttributeMaxDynamicSharedMemorySize, GEMM_SMEM);

    // weight splits (vectorized, idempotent)
    split4_kernel<<<(PROJ_OUT * 1024 / 4 + 255) / 256, 256>>>((const float4*)w_in,
        (__nv_bfloat162*)winh, (__nv_bfloat162*)winl, PROJ_OUT * 1024 / 4);
    split4_kernel<<<(1024 * 2048 / 4 + 255) / 256, 256>>>((const float4*)w_out,
        (__nv_bfloat162*)woh, (__nv_bfloat162*)wol, 1024 * 2048 / 4);
    split4_kernel<<<(4096 * 1024 / 4 + 255) / 256, 256>>>((const float4*)ff_w1,
        (__nv_bfloat162*)w1h, (__nv_bfloat162*)w1l, 4096 * 1024 / 4);
    split4_kernel<<<(1024 * 4096 / 4 + 255) / 256, 256>>>((const float4*)ff_w2,
        (__nv_bfloat162*)w2h, (__nv_bfloat162*)w2l, 1024 * 4096 / 4);

    // 1. h1 = rmsnorm(x) (split)
    rmsnorm_split_kernel<<<BT, 256>>>(x, norm1_w, h1h, h1l);
    // 2. proj = h1 @ w_in^T  (4096 x 4224 x 1024)
    gemm_mma<<<dim3(PROJ_OUT / 128, BT / 128), 256, GEMM_SMEM>>>(h1h, h1l, winh, winl, nullptr, nullptr,
                                                      proj, nullptr, nullptr, PROJ_OUT, DMODEL, 0);
    // 3. fused conv+silu / params / bcpack
    prep_kernel<<<BT, 256>>>(proj, conv_w, conv_b, val, par, bcT);
    // 4. scan
    scan_kernel<<<2 * BQ * NHEADS, 512>>>(bcT, par, val, scan);
    // 5. yg = rmsnorm(scan * silu(gate)) (split)
    gated_norm_split_kernel<<<BT, 256>>>(proj, scan, out_nw, ygh, ygl);
    // 6. x1 = x + yg @ w_out^T  (4096 x 1024 x 2048)
    gemm_mma<<<dim3(DMODEL / 128, BT / 128), 256, GEMM_SMEM>>>(ygh, ygl, woh, wol, nullptr, x,
                                                    x1, nullptr, nullptr, DMODEL, DINNER, 1);
    // 7. h2 = rmsnorm(x1) (split)
    rmsnorm_split_kernel<<<BT, 256>>>(x1, norm2_w, h2h, h2l);
    // 8. ffa = split(gelu(h2 @ ff_w1^T + b1))  (4096 x 4096 x 1024)
    gemm_mma<<<dim3(DFF / 128, BT / 128), 256, GEMM_SMEM>>>(h2h, h2l, w1h, w1l, ff_b1, nullptr,
                                                 nullptr, ffh, ffl, DFF, DMODEL, 2);
    // 9. out = x1 + ffa @ ff_w2^T + b2  (4096 x 1024 x 4096)
    gemm_mma<<<dim3(DMODEL / 128, BT / 128), 256, GEMM_SMEM>>>(ffh, ffl, w2h, w2l, ff_b2, x1,
                                                    out, nullptr, nullptr, DMODEL, DFF, 1);
}

// round 11
// speedup vs baseline: 2.5493x; 1.1553x over previous
#include <cuda_runtime.h>
#include <cuda_fp16.h>
#include <math.h>
#include <stdint.h>

typedef __half f16;

#define BQ 2
#define TQ 2048
#define DMODEL 1024
#define DINNER 2048
#define NHEADS 32
#define DHEAD 64
#define DCONV 4
#define PROJ_OUT 4224
#define BT 4096
#define PARAM_OFF 4096
#define BC_OFF 4160
#define DFF 4096

// ---------------- scratch (device globals; no allocation) ----------------
__device__ float g_proj[(size_t)BT * PROJ_OUT];
__device__ float g_val [(size_t)BT * DINNER];
__device__ float g_par [(size_t)BT * NHEADS * 2];
__device__ float g_bcT [(size_t)BT * 64];
__device__ float g_scan[(size_t)BT * DINNER];
__device__ float g_x1  [BT * DMODEL];
// fp16 activation hi/lo
__device__ f16 g_h1h[BT * DMODEL],         g_h1l[BT * DMODEL];
__device__ f16 g_ygh[(size_t)BT * DINNER], g_ygl[(size_t)BT * DINNER];
__device__ f16 g_h2h[BT * DMODEL],         g_h2l[BT * DMODEL];
__device__ f16 g_ffh[(size_t)BT * DFF],    g_ffl[(size_t)BT * DFF];
// fp16 weights (hi only)
__device__ f16 g_win[PROJ_OUT * 1024];
__device__ f16 g_wo [1024 * 2048];
__device__ f16 g_w1 [4096 * 1024];
__device__ f16 g_w2 [1024 * 4096];

// ---------------- math helpers ----------------
__device__ __forceinline__ float siluf_(float x)    { return x / (1.f + __expf(-x)); }
__device__ __forceinline__ float geluf_(float x) {
    float x3 = x * x * x;
    return 0.5f * x * (1.f + tanhf(0.7978845608028654f * (x + 0.044715f * x3)));
}
__device__ __forceinline__ float sigmoidf_(float x) { return 1.f / (1.f + __expf(-x)); }
__device__ __forceinline__ float softplusf_(float x) {
    return (x > 20.f) ? x : log1pf(expf(x));
}
__device__ __forceinline__ void split1(float v, f16* h, f16* l) {
    f16 hh = __float2half_rn(v);
    *h = hh;
    *l = __float2half_rn(v - __half2float(hh));
}

__device__ __forceinline__ float block_reduce_sum(float v) {
    __shared__ float sh[32];
    int lane = threadIdx.x & 31, wid = threadIdx.x >> 5;
    int nwarps = blockDim.x >> 5;
    #pragma unroll
    for (int m = 16; m > 0; m >>= 1) v += __shfl_xor_sync(0xffffffffu, v, m);
    if (lane == 0) sh[wid] = v;
    __syncthreads();
    if (wid == 0) {
        v = (lane < nwarps) ? sh[lane] : 0.f;
        #pragma unroll
        for (int m = 16; m > 0; m >>= 1) v += __shfl_xor_sync(0xffffffffu, v, m);
        if (lane == 0) sh[0] = v;
    }
    __syncthreads();
    return sh[0];
}

// ---------------- low-level (sm_80-compatible only) ----------------
__device__ __forceinline__ uint32_t smem_u32(const void* p) {
    uint32_t a;
    asm("{ .reg .u64 t; cvta.to.shared.u64 t, %1; cvt.u32.u64 %0, t; }" : "=r"(a) : "l"(p));
    return a;
}
#define CP_ASYNC16(dst, src) \
    asm volatile("cp.async.cg.shared.global [%0], [%1], 16;" :: "r"((uint32_t)(dst)), "l"(src))
#define CP_COMMIT() asm volatile("cp.async.commit_group;" ::: "memory")

__device__ __forceinline__ void ldsm_x4(uint32_t* r, uint32_t addr) {
    asm volatile("ldmatrix.sync.aligned.m8n8.x4.shared.b16 {%0,%1,%2,%3}, [%4];"
                 : "=r"(r[0]), "=r"(r[1]), "=r"(r[2]), "=r"(r[3]) : "r"(addr));
}
__device__ __forceinline__ void ldsm_x2(uint32_t* r, uint32_t addr) {
    asm volatile("ldmatrix.sync.aligned.m8n8.x2.shared.b16 {%0,%1}, [%2];"
                 : "=r"(r[0]), "=r"(r[1]) : "r"(addr));
}
__device__ __forceinline__ void mma16816(float* c, const uint32_t* a, const uint32_t* b) {
    asm volatile("mma.sync.aligned.m16n8k16.row.col.f32.f16.f16.f32 "
                 "{%0,%1,%2,%3}, {%4,%5,%6,%7}, {%8,%9}, {%0,%1,%2,%3};"
                 : "+f"(c[0]), "+f"(c[1]), "+f"(c[2]), "+f"(c[3])
                 : "r"(a[0]), "r"(a[1]), "r"(a[2]), "r"(a[3]), "r"(b[0]), "r"(b[1]));
}

// ---------------- rmsnorm + fp16 split (D=1024, 256 thr) ----------------
__global__ void rmsnorm_split_kernel(const float* __restrict__ x, const float* __restrict__ w,
                                     f16* __restrict__ oh, f16* __restrict__ ol) {
    int row = blockIdx.x;
    int i = threadIdx.x;
    const float4* xr = (const float4*)(x + (size_t)row * DMODEL);
    float4 v = xr[i];
    float ss = v.x * v.x + v.y * v.y + v.z * v.z + v.w * v.w;
    ss = block_reduce_sum(ss);
    float inv = rsqrtf(ss / (float)DMODEL + 1e-6f);
    float4 wv = ((const float4*)w)[i];
    float o0 = v.x * inv * wv.x, o1 = v.y * inv * wv.y;
    float o2 = v.z * inv * wv.z, o3 = v.w * inv * wv.w;
    __half2 h0, h1, l0, l1;
    split1(o0, &h0.x, &l0.x); split1(o1, &h0.y, &l0.y);
    split1(o2, &h1.x, &l1.x); split1(o3, &h1.y, &l1.y);
    __half2* ohp = (__half2*)(oh + (size_t)row * DMODEL);
    __half2* olp = (__half2*)(ol + (size_t)row * DMODEL);
    ohp[2 * i] = h0; ohp[2 * i + 1] = h1;
    olp[2 * i] = l0; olp[2 * i + 1] = l1;
}

// ---------------- gated rmsnorm + fp16 split (DINNER=2048) ----------------
__global__ void gated_norm_split_kernel(const float* __restrict__ proj, const float* __restrict__ scan_y,
                                        const float* __restrict__ w,
                                        f16* __restrict__ oh, f16* __restrict__ ol) {
    int row = blockIdx.x;
    int tid = threadIdx.x;
    const float4* prow = (const float4*)(proj + (size_t)row * PROJ_OUT);
    const float4* sy = (const float4*)(scan_y + (size_t)row * DINNER);
    float4 tv[2];
    float ss = 0.f;
    #pragma unroll
    for (int q = 0; q < 2; ++q) {
        int i = tid + q * 256;
        float4 g = prow[i];
        float4 s = sy[i];
        float4 t;
        t.x = s.x * siluf_(g.x); t.y = s.y * siluf_(g.y);
        t.z = s.z * siluf_(g.z); t.w = s.w * siluf_(g.w);
        tv[q] = t;
        ss += t.x * t.x + t.y * t.y + t.z * t.z + t.w * t.w;
    }
    ss = block_reduce_sum(ss);
    float inv = rsqrtf(ss / (float)DINNER + 1e-6f);
    __half2* ohp = (__half2*)(oh + (size_t)row * DINNER);
    __half2* olp = (__half2*)(ol + (size_t)row * DINNER);
    #pragma unroll
    for (int q = 0; q < 2; ++q) {
        int i = tid + q * 256;
        float4 wv = ((const float4*)w)[i];
        float o0 = tv[q].x * inv * wv.x, o1 = tv[q].y * inv * wv.y;
        float o2 = tv[q].z * inv * wv.z, o3 = tv[q].w * inv * wv.w;
        __half2 h0, h1, l0, l1;
        split1(o0, &h0.x, &l0.x); split1(o1, &h0.y, &l0.y);
        split1(o2, &h1.x, &l1.x); split1(o3, &h1.y, &l1.y);
        ohp[2 * i] = h0; ohp[2 * i + 1] = h1;
        olp[2 * i] = l0; olp[2 * i + 1] = l1;
    }
}

// ---------------- fp32 -> fp16 convert (weights, hi only, vectorized) ----------------
__global__ void cvt4_kernel(const float4* __restrict__ src, __half2* __restrict__ dst, int n4) {
    int i = blockIdx.x * blockDim.x + threadIdx.x;
    if (i >= n4) return;
    float4 v = src[i];
    __half2 h0, h1;
    h0.x = __float2half_rn(v.x); h0.y = __float2half_rn(v.y);
    h1.x = __float2half_rn(v.z); h1.y = __float2half_rn(v.w);
    dst[2 * i] = h0; dst[2 * i + 1] = h1;
}

// ---------------- fused conv+silu / params / bcpack (one block per (b,t)) ----------------
__global__ void prep_kernel(const float* __restrict__ proj, const float* __restrict__ conv_w,
                            const float* __restrict__ conv_b, float* __restrict__ value,
                            float* __restrict__ par, float* __restrict__ bcT) {
    int bt = blockIdx.x;
    int t = bt & (TQ - 1);
    int tid = threadIdx.x;
    const float* prow = proj + (size_t)bt * PROJ_OUT;
    #pragma unroll
    for (int i = 0; i < 8; ++i) {
        int c = tid + i * 256;
        float acc = conv_b[c];
        #pragma unroll
        for (int k = 0; k < DCONV; ++k) {
            int ts = t - (DCONV - 1) + k;
            if (ts >= 0)
                acc += prow[(ts - t) * (ptrdiff_t)PROJ_OUT + DINNER + c] * conv_w[c * DCONV + k];
        }
        value[(size_t)bt * DINNER + c] = siluf_(acc);
    }
    if (tid < 32) {
        int h = tid;
        par[((size_t)bt * NHEADS + h) * 2 + 0] = softplusf_(prow[PARAM_OFF + 2 * h]);
        par[((size_t)bt * NHEADS + h) * 2 + 1] = sigmoidf_(prow[PARAM_OFF + 2 * h + 1]);
    } else if (tid >= 64 && tid < 80) {
        int n = tid - 64;
        float4 v;
        v.x = prow[BC_OFF + n];
        v.y = prow[BC_OFF + 16 + n];
        v.z = prow[BC_OFF + 32 + n];
        v.w = prow[BC_OFF + 48 + n];
        ((float4*)bcT)[(size_t)bt * 16 + n] = v;
    }
}

// ---------------- sequential SSM scan ----------------
__global__ void scan_kernel(const float* __restrict__ bcT, const float* __restrict__ par,
                            const float* __restrict__ value, float* __restrict__ scan_y) {
    int blk = blockIdx.x;
    int bh = blk >> 1;
    int b = bh >> 5;
    int h = bh & 31;
    int half = blk & 1;
    int tid = threadIdx.x;
    int p = half * 32 + (tid >> 4);
    int n = tid & 15;
    float S0 = 0.f, S1 = 0.f;
    const size_t rowbase = (size_t)b * TQ;
    const float4* bc4 = (const float4*)bcT;
    const float2* ad2 = (const float2*)par;
    float4 nbc = bc4[rowbase * 16 + n];
    float2 nad = ad2[rowbase * NHEADS + h];
    float  nu  = value[rowbase * DINNER + h * DHEAD + p];
    for (int t = 0; t < TQ; ++t) {
        float4 bcv = nbc; float2 ad = nad; float u = nu;
        if (t + 1 < TQ) {
            size_t r2 = rowbase + t + 1;
            nbc = bc4[r2 * 16 + n];
            nad = ad2[r2 * NHEADS + h];
            nu  = value[r2 * DINNER + h * DHEAD + p];
        }
        float A = ad.x, dt = ad.y;
        float dtA = dt * A;
        float du = dt * u;
        float s0n = fmaf(-dtA, S1, fmaf(bcv.x, du, S0));
        float s1n = fmaf(dt, S0, fmaf(1.f - dt * dtA, S1, dt * bcv.y * du));
        S0 = s0n; S1 = s1n;
        float y = bcv.z * s0n + bcv.w * s1n;
        y += __shfl_xor_sync(0xffffffffu, y, 8);
        y += __shfl_xor_sync(0xffffffffu, y, 4);
        y += __shfl_xor_sync(0xffffffffu, y, 2);
        y += __shfl_xor_sync(0xffffffffu, y, 1);
        if (n == 0) scan_y[(rowbase + t) * DINNER + h * DHEAD + p] = y;
    }
}

// ---------------- fp16 split-precision GEMM via mma.sync (HMMA) ----------------
// C[M,N] = (Ah + Al) @ W^T : products Ah*W + Al*W (weights plain fp16).
// CTA 128x128, BK=32, 256 threads (8 warps, 64x32 each), 2-stage cp.async.
// mode 0: C = acc ; 1: + bias?/res? ; 2: split(gelu(acc+bias)) -> Oh/Ol
#define ASTRIDE 40                  // f16 per smem row (80B) -> conflict-free ldmatrix
#define TILEB (128 * ASTRIDE * 2)   // bytes per tile (10240)
#define STAGEB (3 * TILEB)          // bytes per stage (30720)
#define GEMM_SMEM (2 * STAGEB)      // 61440
__global__ void __launch_bounds__(256, 2)
gemm_mma(const f16* __restrict__ Ah, const f16* __restrict__ Al,
         const f16* __restrict__ Bh,
         const float* __restrict__ bias, const float* __restrict__ res,
         float* __restrict__ C, f16* __restrict__ Oh, f16* __restrict__ Ol,
         int N, int K, int mode) {
    extern __shared__ __align__(16) f16 dsm[];
    const uint32_t s0 = smem_u32(dsm);
    const int tid = threadIdx.x, wid = tid >> 5, lane = tid & 31;
    const int row0 = blockIdx.y * 128, col0 = blockIdx.x * 128;
    const int wm = wid & 1, wn = wid >> 1;          // 2 x 4 warp grid
    const int nch = K >> 5;

    float acc[4][4][4];
    #pragma unroll
    for (int mt = 0; mt < 4; ++mt)
        #pragma unroll
        for (int nt = 0; nt < 4; ++nt)
            #pragma unroll
            for (int q = 0; q < 4; ++q) acc[mt][nt][q] = 0.f;

    const int lr = tid >> 2, lc = tid & 3;
    const f16* gAh = Ah + (size_t)(row0 + lr) * K + lc * 8;
    const f16* gAl = Al + (size_t)(row0 + lr) * K + lc * 8;
    const f16* gBh = Bh + (size_t)(col0 + lr) * K + lc * 8;
    const uint32_t dst = lr * 80 + lc * 16;

    #define LOAD_CHUNK(stg, k0) do {                                                   \
        uint32_t _b = s0 + (stg) * STAGEB + dst;                                       \
        CP_ASYNC16(_b,                       gAh + (k0));                              \
        CP_ASYNC16(_b + 64 * 80,             gAh + (size_t)64 * K + (k0));             \
        CP_ASYNC16(_b + TILEB,               gAl + (k0));                              \
        CP_ASYNC16(_b + TILEB + 64 * 80,     gAl + (size_t)64 * K + (k0));             \
        CP_ASYNC16(_b + 2 * TILEB,           gBh + (k0));                              \
        CP_ASYNC16(_b + 2 * TILEB + 64 * 80, gBh + (size_t)64 * K + (k0));             \
        CP_COMMIT();                                                                   \
    } while (0)

    LOAD_CHUNK(0, 0);

    const uint32_t a_row = (uint32_t)(wm * 64 + (lane & 15));
    const uint32_t a_coff = (uint32_t)((lane >> 4) * 8);
    const uint32_t b_row = (uint32_t)(wn * 32 + (lane & 7));
    const uint32_t b_coff = (uint32_t)(((lane >> 3) & 1) * 8);

    for (int ch = 0; ch < nch; ++ch) {
        const int stg = ch & 1;
        if (ch + 1 < nch) {
            LOAD_CHUNK(stg ^ 1, (ch + 1) << 5);
            asm volatile("cp.async.wait_group 1;" ::: "memory");
        } else {
            asm volatile("cp.async.wait_group 0;" ::: "memory");
        }
        __syncthreads();

        const uint32_t sb = s0 + stg * STAGEB;
        const uint32_t sAh_ = sb, sAl_ = sb + TILEB, sBh_ = sb + 2 * TILEB;
        #pragma unroll
        for (int ks = 0; ks < 2; ++ks) {
            const uint32_t acol = (ks * 16 + a_coff) * 2;
            const uint32_t bcol = (ks * 16 + b_coff) * 2;
            uint32_t afr[4][4], bh_[4][2];
            #pragma unroll
            for (int nt = 0; nt < 4; ++nt)
                ldsm_x2(bh_[nt], sBh_ + (b_row + nt * 8) * 80 + bcol);
            #pragma unroll
            for (int mt = 0; mt < 4; ++mt)
                ldsm_x4(afr[mt], sAh_ + (a_row + mt * 16) * 80 + acol);
            #pragma unroll
            for (int mt = 0; mt < 4; ++mt)
                #pragma unroll
                for (int nt = 0; nt < 4; ++nt)
                    mma16816(acc[mt][nt], afr[mt], bh_[nt]);
            #pragma unroll
            for (int mt = 0; mt < 4; ++mt)
                ldsm_x4(afr[mt], sAl_ + (a_row + mt * 16) * 80 + acol);   // reuse regs
            #pragma unroll
            for (int mt = 0; mt < 4; ++mt)
                #pragma unroll
                for (int nt = 0; nt < 4; ++nt)
                    mma16816(acc[mt][nt], afr[mt], bh_[nt]);
        }
        __syncthreads();
    }

    // epilogue
    const int er = lane >> 2, ec = (lane & 3) << 1;
    #pragma unroll
    for (int mt = 0; mt < 4; ++mt) {
        #pragma unroll
        for (int nt = 0; nt < 4; ++nt) {
            int gr = row0 + wm * 64 + mt * 16 + er;
            int gc = col0 + wn * 32 + nt * 8 + ec;
            const float* cc = acc[mt][nt];
            #pragma unroll
            for (int half = 0; half < 2; ++half) {
                int r = gr + half * 8;
                float v0 = cc[half * 2 + 0], v1 = cc[half * 2 + 1];
                if (mode == 2) {
                    v0 = geluf_(v0 + bias[gc]);
                    v1 = geluf_(v1 + bias[gc + 1]);
                    __half2 hp, lp;
                    split1(v0, &hp.x, &lp.x);
                    split1(v1, &hp.y, &lp.y);
                    size_t o = (size_t)r * N + gc;
                    *(__half2*)(Oh + o) = hp;
                    *(__half2*)(Ol + o) = lp;
                } else {
                    if (bias) { v0 += bias[gc]; v1 += bias[gc + 1]; }
                    if (res) {
                        const float* rp = res + (size_t)r * N + gc;
                        v0 += rp[0]; v1 += rp[1];
                    }
                    float2 v; v.x = v0; v.y = v1;
                    *(float2*)(C + (size_t)r * N + gc) = v;
                }
            }
        }
    }
}

// ---------------- launch ----------------
extern "C" void kernel_launch(void* const* d_in, const int* in_sizes, int n_in,
                              void* d_out, int out_size) {
    const float* x       = (const float*)d_in[0];
    const float* w_in    = (const float*)d_in[1];
    const float* conv_w  = (const float*)d_in[2];
    const float* conv_b  = (const float*)d_in[3];
    const float* norm1_w = (const float*)d_in[4];
    const float* out_nw  = (const float*)d_in[5];
    const float* w_out   = (const float*)d_in[6];
    const float* norm2_w = (const float*)d_in[7];
    const float* ff_w1   = (const float*)d_in[8];
    const float* ff_b1   = (const float*)d_in[9];
    const float* ff_w2   = (const float*)d_in[10];
    const float* ff_b2   = (const float*)d_in[11];
    float* out = (float*)d_out;

    float *proj, *val, *par, *bcT, *scan, *x1;
    f16 *h1h, *h1l, *ygh, *ygl, *h2h, *h2l, *ffh, *ffl;
    f16 *win, *wo, *w1, *w2;
    cudaGetSymbolAddress((void**)&proj, g_proj);
    cudaGetSymbolAddress((void**)&val,  g_val);
    cudaGetSymbolAddress((void**)&par,  g_par);
    cudaGetSymbolAddress((void**)&bcT,  g_bcT);
    cudaGetSymbolAddress((void**)&scan, g_scan);
    cudaGetSymbolAddress((void**)&x1,   g_x1);
    cudaGetSymbolAddress((void**)&h1h,  g_h1h);  cudaGetSymbolAddress((void**)&h1l, g_h1l);
    cudaGetSymbolAddress((void**)&ygh,  g_ygh);  cudaGetSymbolAddress((void**)&ygl, g_ygl);
    cudaGetSymbolAddress((void**)&h2h,  g_h2h);  cudaGetSymbolAddress((void**)&h2l, g_h2l);
    cudaGetSymbolAddress((void**)&ffh,  g_ffh);  cudaGetSymbolAddress((void**)&ffl, g_ffl);
    cudaGetSymbolAddress((void**)&win,  g_win);
    cudaGetSymbolAddress((void**)&wo,   g_wo);
    cudaGetSymbolAddress((void**)&w1,   g_w1);
    cudaGetSymbolAddress((void**)&w2,   g_w2);

    cudaFuncSetAttribute(gemm_mma, cudaFuncAttributeMaxDynamicSharedMemorySize, GEMM_SMEM);

    // weight fp16 conversion (idempotent)
    cvt4_kernel<<<(PROJ_OUT * 1024 / 4 + 255) / 256, 256>>>((const float4*)w_in,
        (__half2*)win, PROJ_OUT * 1024 / 4);
    cvt4_kernel<<<(1024 * 2048 / 4 + 255) / 256, 256>>>((const float4*)w_out,
        (__half2*)wo, 1024 * 2048 / 4);
    cvt4_kernel<<<(4096 * 1024 / 4 + 255) / 256, 256>>>((const float4*)ff_w1,
        (__half2*)w1, 4096 * 1024 / 4);
    cvt4_kernel<<<(1024 * 4096 / 4 + 255) / 256, 256>>>((const float4*)ff_w2,
        (__half2*)w2, 1024 * 4096 / 4);

    // 1. h1 = rmsnorm(x) (fp16 split)
    rmsnorm_split_kernel<<<BT, 256>>>(x, norm1_w, h1h, h1l);
    // 2. proj = h1 @ w_in^T  (4096 x 4224 x 1024)
    gemm_mma<<<dim3(PROJ_OUT / 128, BT / 128), 256, GEMM_SMEM>>>(h1h, h1l, win, nullptr, nullptr,
                                                      proj, nullptr, nullptr, PROJ_OUT, DMODEL, 0);
    // 3. fused conv+silu / params / bcpack
    prep_kernel<<<BT, 256>>>(proj, conv_w, conv_b, val, par, bcT);
    // 4. scan
    scan_kernel<<<2 * BQ * NHEADS, 512>>>(bcT, par, val, scan);
    // 5. yg = rmsnorm(scan * silu(gate)) (fp16 split)
    gated_norm_split_kernel<<<BT, 256>>>(proj, scan, out_nw, ygh, ygl);
    // 6. x1 = x + yg @ w_out^T  (4096 x 1024 x 2048)
    gemm_mma<<<dim3(DMODEL / 128, BT / 128), 256, GEMM_SMEM>>>(ygh, ygl, wo, nullptr, x,
                                                    x1, nullptr, nullptr, DMODEL, DINNER, 1);
    // 7. h2 = rmsnorm(x1) (fp16 split)
    rmsnorm_split_kernel<<<BT, 256>>>(x1, norm2_w, h2h, h2l);
    // 8. ffa = split(gelu(h2 @ ff_w1^T + b1))  (4096 x 4096 x 1024)
    gemm_mma<<<dim3(DFF / 128, BT / 128), 256, GEMM_SMEM>>>(h2h, h2l, w1, ff_b1, nullptr,
                                                 nullptr, ffh, ffl, DFF, DMODEL, 2);
    // 9. out = x1 + ffa @ ff_w2^T + b2  (4096 x 1024 x 4096)
    gemm_mma<<<dim3(DMODEL / 128, BT / 128), 256, GEMM_SMEM>>>(ffh, ffl, w2, ff_b2, x1,
                                                    out, nullptr, nullptr, DMODEL, DFF, 1);
}

// round 12
// speedup vs baseline: 2.5501x; 1.0003x over previous
#include <cuda_runtime.h>
#include <cuda_fp16.h>
#include <math.h>
#include <stdint.h>

typedef __half f16;

#define BQ 2
#define TQ 2048
#define DMODEL 1024
#define DINNER 2048
#define NHEADS 32
#define DHEAD 64
#define DCONV 4
#define PROJ_OUT 4224
#define BT 4096
#define PARAM_OFF 4096
#define BC_OFF 4160
#define DFF 4096

// ---------------- scratch (device globals; no allocation) ----------------
__device__ float g_proj[(size_t)BT * PROJ_OUT];
__device__ float g_val [(size_t)BT * DINNER];
__device__ float g_par [(size_t)BT * NHEADS * 2];
__device__ float g_bcT [(size_t)BT * 64];
__device__ float g_scan[(size_t)BT * DINNER];
__device__ float g_x1  [BT * DMODEL];
// fp16 activation hi/lo
__device__ f16 g_h1h[BT * DMODEL],         g_h1l[BT * DMODEL];
__device__ f16 g_ygh[(size_t)BT * DINNER], g_ygl[(size_t)BT * DINNER];
__device__ f16 g_h2h[BT * DMODEL],         g_h2l[BT * DMODEL];
__device__ f16 g_ffh[(size_t)BT * DFF],    g_ffl[(size_t)BT * DFF];
// fp16 weights (hi only)
__device__ f16 g_win[PROJ_OUT * 1024];
__device__ f16 g_wo [1024 * 2048];
__device__ f16 g_w1 [4096 * 1024];
__device__ f16 g_w2 [1024 * 4096];
// fp16 hi/lo split of w_in tail rows (4096..4223) for high-precision scan params
__device__ f16 g_wth[128 * 1024], g_wtl[128 * 1024];

// ---------------- math helpers ----------------
__device__ __forceinline__ float siluf_(float x)    { return x / (1.f + __expf(-x)); }
__device__ __forceinline__ float geluf_(float x) {
    float x3 = x * x * x;
    return 0.5f * x * (1.f + tanhf(0.7978845608028654f * (x + 0.044715f * x3)));
}
__device__ __forceinline__ float sigmoidf_(float x) { return 1.f / (1.f + __expf(-x)); }
__device__ __forceinline__ float softplusf_(float x) {
    return (x > 20.f) ? x : log1pf(expf(x));
}
__device__ __forceinline__ void split1(float v, f16* h, f16* l) {
    f16 hh = __float2half_rn(v);
    *h = hh;
    *l = __float2half_rn(v - __half2float(hh));
}

__device__ __forceinline__ float block_reduce_sum(float v) {
    __shared__ float sh[32];
    int lane = threadIdx.x & 31, wid = threadIdx.x >> 5;
    int nwarps = blockDim.x >> 5;
    #pragma unroll
    for (int m = 16; m > 0; m >>= 1) v += __shfl_xor_sync(0xffffffffu, v, m);
    if (lane == 0) sh[wid] = v;
    __syncthreads();
    if (wid == 0) {
        v = (lane < nwarps) ? sh[lane] : 0.f;
        #pragma unroll
        for (int m = 16; m > 0; m >>= 1) v += __shfl_xor_sync(0xffffffffu, v, m);
        if (lane == 0) sh[0] = v;
    }
    __syncthreads();
    return sh[0];
}

// ---------------- low-level (sm_80-compatible only) ----------------
__device__ __forceinline__ uint32_t smem_u32(const void* p) {
    uint32_t a;
    asm("{ .reg .u64 t; cvta.to.shared.u64 t, %1; cvt.u32.u64 %0, t; }" : "=r"(a) : "l"(p));
    return a;
}
#define CP_ASYNC16(dst, src) \
    asm volatile("cp.async.cg.shared.global [%0], [%1], 16;" :: "r"((uint32_t)(dst)), "l"(src))
#define CP_COMMIT() asm volatile("cp.async.commit_group;" ::: "memory")

__device__ __forceinline__ void ldsm_x4(uint32_t* r, uint32_t addr) {
    asm volatile("ldmatrix.sync.aligned.m8n8.x4.shared.b16 {%0,%1,%2,%3}, [%4];"
                 : "=r"(r[0]), "=r"(r[1]), "=r"(r[2]), "=r"(r[3]) : "r"(addr));
}
__device__ __forceinline__ void ldsm_x2(uint32_t* r, uint32_t addr) {
    asm volatile("ldmatrix.sync.aligned.m8n8.x2.shared.b16 {%0,%1}, [%2];"
                 : "=r"(r[0]), "=r"(r[1]) : "r"(addr));
}
__device__ __forceinline__ void mma16816(float* c, const uint32_t* a, const uint32_t* b) {
    asm volatile("mma.sync.aligned.m16n8k16.row.col.f32.f16.f16.f32 "
                 "{%0,%1,%2,%3}, {%4,%5,%6,%7}, {%8,%9}, {%0,%1,%2,%3};"
                 : "+f"(c[0]), "+f"(c[1]), "+f"(c[2]), "+f"(c[3])
                 : "r"(a[0]), "r"(a[1]), "r"(a[2]), "r"(a[3]), "r"(b[0]), "r"(b[1]));
}

// ---------------- rmsnorm + fp16 split (D=1024, 256 thr) ----------------
__global__ void rmsnorm_split_kernel(const float* __restrict__ x, const float* __restrict__ w,
                                     f16* __restrict__ oh, f16* __restrict__ ol) {
    int row = blockIdx.x;
    int i = threadIdx.x;
    const float4* xr = (const float4*)(x + (size_t)row * DMODEL);
    float4 v = xr[i];
    float ss = v.x * v.x + v.y * v.y + v.z * v.z + v.w * v.w;
    ss = block_reduce_sum(ss);
    float inv = rsqrtf(ss / (float)DMODEL + 1e-6f);
    float4 wv = ((const float4*)w)[i];
    float o0 = v.x * inv * wv.x, o1 = v.y * inv * wv.y;
    float o2 = v.z * inv * wv.z, o3 = v.w * inv * wv.w;
    __half2 h0, h1, l0, l1;
    split1(o0, &h0.x, &l0.x); split1(o1, &h0.y, &l0.y);
    split1(o2, &h1.x, &l1.x); split1(o3, &h1.y, &l1.y);
    __half2* ohp = (__half2*)(oh + (size_t)row * DMODEL);
    __half2* olp = (__half2*)(ol + (size_t)row * DMODEL);
    ohp[2 * i] = h0; ohp[2 * i + 1] = h1;
    olp[2 * i] = l0; olp[2 * i + 1] = l1;
}

// ---------------- gated rmsnorm + fp16 split (DINNER=2048) ----------------
__global__ void gated_norm_split_kernel(const float* __restrict__ proj, const float* __restrict__ scan_y,
                                        const float* __restrict__ w,
                                        f16* __restrict__ oh, f16* __restrict__ ol) {
    int row = blockIdx.x;
    int tid = threadIdx.x;
    const float4* prow = (const float4*)(proj + (size_t)row * PROJ_OUT);
    const float4* sy = (const float4*)(scan_y + (size_t)row * DINNER);
    float4 tv[2];
    float ss = 0.f;
    #pragma unroll
    for (int q = 0; q < 2; ++q) {
        int i = tid + q * 256;
        float4 g = prow[i];
        float4 s = sy[i];
        float4 t;
        t.x = s.x * siluf_(g.x); t.y = s.y * siluf_(g.y);
        t.z = s.z * siluf_(g.z); t.w = s.w * siluf_(g.w);
        tv[q] = t;
        ss += t.x * t.x + t.y * t.y + t.z * t.z + t.w * t.w;
    }
    ss = block_reduce_sum(ss);
    float inv = rsqrtf(ss / (float)DINNER + 1e-6f);
    __half2* ohp = (__half2*)(oh + (size_t)row * DINNER);
    __half2* olp = (__half2*)(ol + (size_t)row * DINNER);
    #pragma unroll
    for (int q = 0; q < 2; ++q) {
        int i = tid + q * 256;
        float4 wv = ((const float4*)w)[i];
        float o0 = tv[q].x * inv * wv.x, o1 = tv[q].y * inv * wv.y;
        float o2 = tv[q].z * inv * wv.z, o3 = tv[q].w * inv * wv.w;
        __half2 h0, h1, l0, l1;
        split1(o0, &h0.x, &l0.x); split1(o1, &h0.y, &l0.y);
        split1(o2, &h1.x, &l1.x); split1(o3, &h1.y, &l1.y);
        ohp[2 * i] = h0; ohp[2 * i + 1] = h1;
        olp[2 * i] = l0; olp[2 * i + 1] = l1;
    }
}

// ---------------- fp32 -> fp16 convert (weights, hi only, vectorized) ----------------
__global__ void cvt4_kernel(const float4* __restrict__ src, __half2* __restrict__ dst, int n4) {
    int i = blockIdx.x * blockDim.x + threadIdx.x;
    if (i >= n4) return;
    float4 v = src[i];
    __half2 h0, h1;
    h0.x = __float2half_rn(v.x); h0.y = __float2half_rn(v.y);
    h1.x = __float2half_rn(v.z); h1.y = __float2half_rn(v.w);
    dst[2 * i] = h0; dst[2 * i + 1] = h1;
}

// ---------------- fp32 -> fp16 hi/lo split (vectorized) ----------------
__global__ void split4_kernel(const float4* __restrict__ src, __half2* __restrict__ hi,
                              __half2* __restrict__ lo, int n4) {
    int i = blockIdx.x * blockDim.x + threadIdx.x;
    if (i >= n4) return;
    float4 v = src[i];
    __half2 h0, h1, l0, l1;
    split1(v.x, &h0.x, &l0.x); split1(v.y, &h0.y, &l0.y);
    split1(v.z, &h1.x, &l1.x); split1(v.w, &h1.y, &l1.y);
    hi[2 * i] = h0; hi[2 * i + 1] = h1;
    lo[2 * i] = l0; lo[2 * i + 1] = l1;
}

// ---------------- fused conv+silu / params / bcpack (one block per (b,t)) ----------------
__global__ void prep_kernel(const float* __restrict__ proj, const float* __restrict__ conv_w,
                            const float* __restrict__ conv_b, float* __restrict__ value,
                            float* __restrict__ par, float* __restrict__ bcT) {
    int bt = blockIdx.x;
    int t = bt & (TQ - 1);
    int tid = threadIdx.x;
    const float* prow = proj + (size_t)bt * PROJ_OUT;
    #pragma unroll
    for (int i = 0; i < 8; ++i) {
        int c = tid + i * 256;
        float acc = conv_b[c];
        #pragma unroll
        for (int k = 0; k < DCONV; ++k) {
            int ts = t - (DCONV - 1) + k;
            if (ts >= 0)
                acc += prow[(ts - t) * (ptrdiff_t)PROJ_OUT + DINNER + c] * conv_w[c * DCONV + k];
        }
        value[(size_t)bt * DINNER + c] = siluf_(acc);
    }
    if (tid < 32) {
        int h = tid;
        par[((size_t)bt * NHEADS + h) * 2 + 0] = softplusf_(prow[PARAM_OFF + 2 * h]);
        par[((size_t)bt * NHEADS + h) * 2 + 1] = sigmoidf_(prow[PARAM_OFF + 2 * h + 1]);
    } else if (tid >= 64 && tid < 80) {
        int n = tid - 64;
        float4 v;
        v.x = prow[BC_OFF + n];
        v.y = prow[BC_OFF + 16 + n];
        v.z = prow[BC_OFF + 32 + n];
        v.w = prow[BC_OFF + 48 + n];
        ((float4*)bcT)[(size_t)bt * 16 + n] = v;
    }
}

// ---------------- sequential SSM scan ----------------
__global__ void scan_kernel(const float* __restrict__ bcT, const float* __restrict__ par,
                            const float* __restrict__ value, float* __restrict__ scan_y) {
    int blk = blockIdx.x;
    int bh = blk >> 1;
    int b = bh >> 5;
    int h = bh & 31;
    int half = blk & 1;
    int tid = threadIdx.x;
    int p = half * 32 + (tid >> 4);
    int n = tid & 15;
    float S0 = 0.f, S1 = 0.f;
    const size_t rowbase = (size_t)b * TQ;
    const float4* bc4 = (const float4*)bcT;
    const float2* ad2 = (const float2*)par;
    float4 nbc = bc4[rowbase * 16 + n];
    float2 nad = ad2[rowbase * NHEADS + h];
    float  nu  = value[rowbase * DINNER + h * DHEAD + p];
    for (int t = 0; t < TQ; ++t) {
        float4 bcv = nbc; float2 ad = nad; float u = nu;
        if (t + 1 < TQ) {
            size_t r2 = rowbase + t + 1;
            nbc = bc4[r2 * 16 + n];
            nad = ad2[r2 * NHEADS + h];
            nu  = value[r2 * DINNER + h * DHEAD + p];
        }
        float A = ad.x, dt = ad.y;
        float dtA = dt * A;
        float du = dt * u;
        float s0n = fmaf(-dtA, S1, fmaf(bcv.x, du, S0));
        float s1n = fmaf(dt, S0, fmaf(1.f - dt * dtA, S1, dt * bcv.y * du));
        S0 = s0n; S1 = s1n;
        float y = bcv.z * s0n + bcv.w * s1n;
        y += __shfl_xor_sync(0xffffffffu, y, 8);
        y += __shfl_xor_sync(0xffffffffu, y, 4);
        y += __shfl_xor_sync(0xffffffffu, y, 2);
        y += __shfl_xor_sync(0xffffffffu, y, 1);
        if (n == 0) scan_y[(rowbase + t) * DINNER + h * DHEAD + p] = y;
    }
}

// ---------------- fp16 2-product GEMM: 3-stage, single sync per chunk ----------------
// C[M,cols] = (Ah + Al) @ W^T. CTA 128x128, BK=32, 8 warps (64x32), 3-stage cp.async.
// N = leading dim of C (may exceed covered cols). mode 0: raw ; 1: +bias?/res? ;
// 2: split(gelu(acc+bias)) -> Oh/Ol
#define TILEB 10240                 // 128 rows x 80B
#define STAGEB (3 * TILEB)          // 30720
#define NST 3
#define GEMM_SMEM (NST * STAGEB)    // 92160
__global__ void __launch_bounds__(256, 2)
gemm_mma2(const f16* __restrict__ Ah, const f16* __restrict__ Al,
          const f16* __restrict__ Bh,
          const float* __restrict__ bias, const float* __restrict__ res,
          float* __restrict__ C, f16* __restrict__ Oh, f16* __restrict__ Ol,
          int N, int K, int mode) {
    extern __shared__ __align__(16) f16 dsm[];
    const uint32_t s0 = smem_u32(dsm);
    const int tid = threadIdx.x, wid = tid >> 5, lane = tid & 31;
    const int row0 = blockIdx.y * 128, col0 = blockIdx.x * 128;
    const int wm = wid & 1, wn = wid >> 1;          // 2 x 4 warp grid (64x32 tiles)
    const int nch = K >> 5;

    float acc[4][4][4];
    #pragma unroll
    for (int mt = 0; mt < 4; ++mt)
        #pragma unroll
        for (int nt = 0; nt < 4; ++nt)
            #pragma unroll
            for (int q = 0; q < 4; ++q) acc[mt][nt][q] = 0.f;

    const int lr = tid >> 2, lc = tid & 3;
    const f16* gAh = Ah + (size_t)(row0 + lr) * K + lc * 8;
    const f16* gAl = Al + (size_t)(row0 + lr) * K + lc * 8;
    const f16* gBh = Bh + (size_t)(col0 + lr) * K + lc * 8;
    const uint32_t dst = lr * 80 + lc * 16;

    #define LOAD_CHUNK2(stg, k0) do {                                                  \
        uint32_t _b = s0 + (stg) * STAGEB + dst;                                       \
        CP_ASYNC16(_b,                       gAh + (k0));                              \
        CP_ASYNC16(_b + 64 * 80,             gAh + (size_t)64 * K + (k0));             \
        CP_ASYNC16(_b + TILEB,               gAl + (k0));                              \
        CP_ASYNC16(_b + TILEB + 64 * 80,     gAl + (size_t)64 * K + (k0));             \
        CP_ASYNC16(_b + 2 * TILEB,           gBh + (k0));                              \
        CP_ASYNC16(_b + 2 * TILEB + 64 * 80, gBh + (size_t)64 * K + (k0));             \
        CP_COMMIT();                                                                   \
    } while (0)

    LOAD_CHUNK2(0, 0);
    LOAD_CHUNK2(1, 32);

    const uint32_t a_row = (uint32_t)(wm * 64 + (lane & 15));
    const uint32_t a_coff = (uint32_t)((lane >> 4) * 8);
    // B x4 layout: lanes 0-7 -> n0-7 kLow, 8-15 -> n0-7 kHigh, 16-23 -> n8-15 kLow, 24-31 -> n8-15 kHigh
    const uint32_t b_row2 = (uint32_t)(wn * 32 + (lane & 7) + (((lane >> 4) & 1) << 3));
    const uint32_t b_coff = (uint32_t)(((lane >> 3) & 1) * 8);

    for (int ch = 0; ch < nch; ++ch) {
        if (ch + 1 < nch)
            asm volatile("cp.async.wait_group 1;" ::: "memory");
        else
            asm volatile("cp.async.wait_group 0;" ::: "memory");
        __syncthreads();                    // stage ch ready; all warps done with ch-1
        if (ch + 2 < nch)
            LOAD_CHUNK2((ch + 2) % NST, (ch + 2) << 5);

        const uint32_t sb = s0 + (ch % NST) * STAGEB;
        const uint32_t sAh_ = sb, sAl_ = sb + TILEB, sBh_ = sb + 2 * TILEB;
        #pragma unroll
        for (int ks = 0; ks < 2; ++ks) {
            const uint32_t acol = (ks * 16 + a_coff) * 2;
            const uint32_t bcol = (ks * 16 + b_coff) * 2;
            uint32_t afr[4][4], bfr[4][2];
            #pragma unroll
            for (int q = 0; q < 2; ++q) {
                uint32_t tmp[4];
                ldsm_x4(tmp, sBh_ + (b_row2 + q * 16) * 80 + bcol);
                bfr[2 * q][0] = tmp[0]; bfr[2 * q][1] = tmp[1];
                bfr[2 * q + 1][0] = tmp[2]; bfr[2 * q + 1][1] = tmp[3];
            }
            #pragma unroll
            for (int mt = 0; mt < 4; ++mt)
                ldsm_x4(afr[mt], sAh_ + (a_row + mt * 16) * 80 + acol);
            #pragma unroll
            for (int mt = 0; mt < 4; ++mt)
                #pragma unroll
                for (int nt = 0; nt < 4; ++nt)
                    mma16816(acc[mt][nt], afr[mt], bfr[nt]);
            #pragma unroll
            for (int mt = 0; mt < 4; ++mt)
                ldsm_x4(afr[mt], sAl_ + (a_row + mt * 16) * 80 + acol);   // reuse regs
            #pragma unroll
            for (int mt = 0; mt < 4; ++mt)
                #pragma unroll
                for (int nt = 0; nt < 4; ++nt)
                    mma16816(acc[mt][nt], afr[mt], bfr[nt]);
        }
    }

    // epilogue
    const int er = lane >> 2, ec = (lane & 3) << 1;
    #pragma unroll
    for (int mt = 0; mt < 4; ++mt) {
        #pragma unroll
        for (int nt = 0; nt < 4; ++nt) {
            int gr = row0 + wm * 64 + mt * 16 + er;
            int gc = col0 + wn * 32 + nt * 8 + ec;
            const float* cc = acc[mt][nt];
            #pragma unroll
            for (int half = 0; half < 2; ++half) {
                int r = gr + half * 8;
                float v0 = cc[half * 2 + 0], v1 = cc[half * 2 + 1];
                if (mode == 2) {
                    v0 = geluf_(v0 + bias[gc]);
                    v1 = geluf_(v1 + bias[gc + 1]);
                    __half2 hp, lp;
                    split1(v0, &hp.x, &lp.x);
                    split1(v1, &hp.y, &lp.y);
                    size_t o = (size_t)r * N + gc;
                    *(__half2*)(Oh + o) = hp;
                    *(__half2*)(Ol + o) = lp;
                } else {
                    if (bias) { v0 += bias[gc]; v1 += bias[gc + 1]; }
                    if (res) {
                        const float* rp = res + (size_t)r * N + gc;
                        v0 += rp[0]; v1 += rp[1];
                    }
                    float2 v; v.x = v0; v.y = v1;
                    *(float2*)(C + (size_t)r * N + gc) = v;
                }
            }
        }
    }
}

// ---------------- fp16 3-product GEMM (high precision; small tail use) ----------------
// C = Ah*Wh + Al*Wh + Ah*Wl. 2-stage, 4 tiles/stage. ldN = row stride of C.
#define STAGEB3 (4 * TILEB)             // 40960
#define GEMM3_SMEM (2 * STAGEB3)        // 81920
__global__ void __launch_bounds__(256, 2)
gemm_mma3(const f16* __restrict__ Ah, const f16* __restrict__ Al,
          const f16* __restrict__ Bh, const f16* __restrict__ Bl,
          float* __restrict__ C, int ldN, int K) {
    extern __shared__ __align__(16) f16 dsm[];
    const uint32_t s0 = smem_u32(dsm);
    const int tid = threadIdx.x, wid = tid >> 5, lane = tid & 31;
    const int row0 = blockIdx.y * 128, col0 = blockIdx.x * 128;
    const int wm = wid & 1, wn = wid >> 1;
    const int nch = K >> 5;

    float acc[4][4][4];
    #pragma unroll
    for (int mt = 0; mt < 4; ++mt)
        #pragma unroll
        for (int nt = 0; nt < 4; ++nt)
            #pragma unroll
            for (int q = 0; q < 4; ++q) acc[mt][nt][q] = 0.f;

    const int lr = tid >> 2, lc = tid & 3;
    const f16* gAh = Ah + (size_t)(row0 + lr) * K + lc * 8;
    const f16* gAl = Al + (size_t)(row0 + lr) * K + lc * 8;
    const f16* gBh = Bh + (size_t)(col0 + lr) * K + lc * 8;
    const f16* gBl = Bl + (size_t)(col0 + lr) * K + lc * 8;
    const uint32_t dst = lr * 80 + lc * 16;

    #define LOAD_CHUNK3(stg, k0) do {                                                  \
        uint32_t _b = s0 + (stg) * STAGEB3 + dst;                                      \
        CP_ASYNC16(_b,                       gAh + (k0));                              \
        CP_ASYNC16(_b + 64 * 80,             gAh + (size_t)64 * K + (k0));             \
        CP_ASYNC16(_b + TILEB,               gAl + (k0));                              \
        CP_ASYNC16(_b + TILEB + 64 * 80,     gAl + (size_t)64 * K + (k0));             \
        CP_ASYNC16(_b + 2 * TILEB,           gBh + (k0));                              \
        CP_ASYNC16(_b + 2 * TILEB + 64 * 80, gBh + (size_t)64 * K + (k0));             \
        CP_ASYNC16(_b + 3 * TILEB,           gBl + (k0));                              \
        CP_ASYNC16(_b + 3 * TILEB + 64 * 80, gBl + (size_t)64 * K + (k0));             \
        CP_COMMIT();                                                                   \
    } while (0)

    LOAD_CHUNK3(0, 0);

    const uint32_t a_row = (uint32_t)(wm * 64 + (lane & 15));
    const uint32_t a_coff = (uint32_t)((lane >> 4) * 8);
    const uint32_t b_row = (uint32_t)(wn * 32 + (lane & 7));
    const uint32_t b_coff = (uint32_t)(((lane >> 3) & 1) * 8);

    for (int ch = 0; ch < nch; ++ch) {
        const int stg = ch & 1;
        if (ch + 1 < nch) {
            LOAD_CHUNK3(stg ^ 1, (ch + 1) << 5);
            asm volatile("cp.async.wait_group 1;" ::: "memory");
        } else {
            asm volatile("cp.async.wait_group 0;" ::: "memory");
        }
        __syncthreads();

        const uint32_t sb = s0 + stg * STAGEB3;
        const uint32_t sAh_ = sb, sAl_ = sb + TILEB, sBh_ = sb + 2 * TILEB, sBl_ = sb + 3 * TILEB;
        #pragma unroll
        for (int ks = 0; ks < 2; ++ks) {
            const uint32_t acol = (ks * 16 + a_coff) * 2;
            const uint32_t bcol = (ks * 16 + b_coff) * 2;
            uint32_t afr[4][4], bh_[4][2], bl_[4][2];
            #pragma unroll
            for (int nt = 0; nt < 4; ++nt) {
                ldsm_x2(bh_[nt], sBh_ + (b_row + nt * 8) * 80 + bcol);
                ldsm_x2(bl_[nt], sBl_ + (b_row + nt * 8) * 80 + bcol);
            }
            #pragma unroll
            for (int mt = 0; mt < 4; ++mt)
                ldsm_x4(afr[mt], sAh_ + (a_row + mt * 16) * 80 + acol);
            #pragma unroll
            for (int mt = 0; mt < 4; ++mt)
                #pragma unroll
                for (int nt = 0; nt < 4; ++nt) {
                    mma16816(acc[mt][nt], afr[mt], bh_[nt]);
                    mma16816(acc[mt][nt], afr[mt], bl_[nt]);
                }
            #pragma unroll
            for (int mt = 0; mt < 4; ++mt)
                ldsm_x4(afr[mt], sAl_ + (a_row + mt * 16) * 80 + acol);
            #pragma unroll
            for (int mt = 0; mt < 4; ++mt)
                #pragma unroll
                for (int nt = 0; nt < 4; ++nt)
                    mma16816(acc[mt][nt], afr[mt], bh_[nt]);
        }
        __syncthreads();
    }

    const int er = lane >> 2, ec = (lane & 3) << 1;
    #pragma unroll
    for (int mt = 0; mt < 4; ++mt) {
        #pragma unroll
        for (int nt = 0; nt < 4; ++nt) {
            int gr = row0 + wm * 64 + mt * 16 + er;
            int gc = col0 + wn * 32 + nt * 8 + ec;
            const float* cc = acc[mt][nt];
            #pragma unroll
            for (int half = 0; half < 2; ++half) {
                int r = gr + half * 8;
                float2 v; v.x = cc[half * 2 + 0]; v.y = cc[half * 2 + 1];
                *(float2*)(C + (size_t)r * ldN + gc) = v;
            }
        }
    }
}

// ---------------- launch ----------------
extern "C" void kernel_launch(void* const* d_in, const int* in_sizes, int n_in,
                              void* d_out, int out_size) {
    const float* x       = (const float*)d_in[0];
    const float* w_in    = (const float*)d_in[1];
    const float* conv_w  = (const float*)d_in[2];
    const float* conv_b  = (const float*)d_in[3];
    const float* norm1_w = (const float*)d_in[4];
    const float* out_nw  = (const float*)d_in[5];
    const float* w_out   = (const float*)d_in[6];
    const float* norm2_w = (const float*)d_in[7];
    const float* ff_w1   = (const float*)d_in[8];
    const float* ff_b1   = (const float*)d_in[9];
    const float* ff_w2   = (const float*)d_in[10];
    const float* ff_b2   = (const float*)d_in[11];
    float* out = (float*)d_out;

    float *proj, *val, *par, *bcT, *scan, *x1;
    f16 *h1h, *h1l, *ygh, *ygl, *h2h, *h2l, *ffh, *ffl;
    f16 *win, *wo, *w1, *w2, *wth, *wtl;
    cudaGetSymbolAddress((void**)&proj, g_proj);
    cudaGetSymbolAddress((void**)&val,  g_val);
    cudaGetSymbolAddress((void**)&par,  g_par);
    cudaGetSymbolAddress((void**)&bcT,  g_bcT);
    cudaGetSymbolAddress((void**)&scan, g_scan);
    cudaGetSymbolAddress((void**)&x1,   g_x1);
    cudaGetSymbolAddress((void**)&h1h,  g_h1h);  cudaGetSymbolAddress((void**)&h1l, g_h1l);
    cudaGetSymbolAddress((void**)&ygh,  g_ygh);  cudaGetSymbolAddress((void**)&ygl, g_ygl);
    cudaGetSymbolAddress((void**)&h2h,  g_h2h);  cudaGetSymbolAddress((void**)&h2l, g_h2l);
    cudaGetSymbolAddress((void**)&ffh,  g_ffh);  cudaGetSymbolAddress((void**)&ffl, g_ffl);
    cudaGetSymbolAddress((void**)&win,  g_win);
    cudaGetSymbolAddress((void**)&wo,   g_wo);
    cudaGetSymbolAddress((void**)&w1,   g_w1);
    cudaGetSymbolAddress((void**)&w2,   g_w2);
    cudaGetSymbolAddress((void**)&wth,  g_wth);
    cudaGetSymbolAddress((void**)&wtl,  g_wtl);

    cudaFuncSetAttribute(gemm_mma2, cudaFuncAttributeMaxDynamicSharedMemorySize, GEMM_SMEM);
    cudaFuncSetAttribute(gemm_mma3, cudaFuncAttributeMaxDynamicSharedMemorySize, GEMM3_SMEM);

    // weight fp16 conversion (idempotent)
    cvt4_kernel<<<(PROJ_OUT * 1024 / 4 + 255) / 256, 256>>>((const float4*)w_in,
        (__half2*)win, PROJ_OUT * 1024 / 4);
    cvt4_kernel<<<(1024 * 2048 / 4 + 255) / 256, 256>>>((const float4*)w_out,
        (__half2*)wo, 1024 * 2048 / 4);
    cvt4_kernel<<<(4096 * 1024 / 4 + 255) / 256, 256>>>((const float4*)ff_w1,
        (__half2*)w1, 4096 * 1024 / 4);
    cvt4_kernel<<<(1024 * 4096 / 4 + 255) / 256, 256>>>((const float4*)ff_w2,
        (__half2*)w2, 1024 * 4096 / 4);
    // hi/lo split of w_in tail rows (scan-parameter columns)
    split4_kernel<<<(128 * 1024 / 4 + 255) / 256, 256>>>(
        (const float4*)(w_in + (size_t)4096 * 1024), (__half2*)wth, (__half2*)wtl, 128 * 1024 / 4);

    // 1. h1 = rmsnorm(x) (fp16 split)
    rmsnorm_split_kernel<<<BT, 256>>>(x, norm1_w, h1h, h1l);
    // 2a. proj[:, :4096] = h1 @ w_in[:4096]^T  (2-product)
    gemm_mma2<<<dim3(32, BT / 128), 256, GEMM_SMEM>>>(h1h, h1l, win, nullptr, nullptr,
                                                      proj, nullptr, nullptr, PROJ_OUT, DMODEL, 0);
    // 2b. proj[:, 4096:] = h1 @ w_in[4096:]^T  (3-product, scan params need precision)
    gemm_mma3<<<dim3(1, BT / 128), 256, GEMM3_SMEM>>>(h1h, h1l, wth, wtl,
                                                      proj + 4096, PROJ_OUT, DMODEL);
    // 3. fused conv+silu / params / bcpack
    prep_kernel<<<BT, 256>>>(proj, conv_w, conv_b, val, par, bcT);
    // 4. scan
    scan_kernel<<<2 * BQ * NHEADS, 512>>>(bcT, par, val, scan);
    // 5. yg = rmsnorm(scan * silu(gate)) (fp16 split)
    gated_norm_split_kernel<<<BT, 256>>>(proj, scan, out_nw, ygh, ygl);
    // 6. x1 = x + yg @ w_out^T  (4096 x 1024 x 2048)
    gemm_mma2<<<dim3(DMODEL / 128, BT / 128), 256, GEMM_SMEM>>>(ygh, ygl, wo, nullptr, x,
                                                    x1, nullptr, nullptr, DMODEL, DINNER, 1);
    // 7. h2 = rmsnorm(x1) (fp16 split)
    rmsnorm_split_kernel<<<BT, 256>>>(x1, norm2_w, h2h, h2l);
    // 8. ffa = split(gelu(h2 @ ff_w1^T + b1))  (4096 x 4096 x 1024)
    gemm_mma2<<<dim3(DFF / 128, BT / 128), 256, GEMM_SMEM>>>(h2h, h2l, w1, ff_b1, nullptr,
                                                 nullptr, ffh, ffl, DFF, DMODEL, 2);
    // 9. out = x1 + ffa @ ff_w2^T + b2  (4096 x 1024 x 4096)
    gemm_mma2<<<dim3(DMODEL / 128, BT / 128), 256, GEMM_SMEM>>>(ffh, ffl, w2, ff_b2, x1,
                                                    out, nullptr, nullptr, DMODEL, DFF, 1);
}

// round 13
// speedup vs baseline: 3.0946x; 1.2135x over previous
#include <cuda_runtime.h>
#include <cuda_fp16.h>
#include <math.h>
#include <stdint.h>

typedef __half f16;

#define BQ 2
#define TQ 2048
#define DMODEL 1024
#define DINNER 2048
#define NHEADS 32
#define DHEAD 64
#define DCONV 4
#define PROJ_OUT 4224
#define BT 4096
#define PARAM_OFF 4096
#define BC_OFF 4160
#define DFF 4096

// ---------------- scratch (device globals; no allocation) ----------------
__device__ float g_proj[(size_t)BT * PROJ_OUT];
__device__ float g_val [(size_t)BT * DINNER];
__device__ float g_par [(size_t)BT * NHEADS * 2];
__device__ float g_bcT [(size_t)BT * 64];
__device__ float g_scan[(size_t)BT * DINNER];
__device__ float g_x1  [BT * DMODEL];
// fp16 activations
__device__ f16 g_h1h[BT * DMODEL],         g_h1l[BT * DMODEL];
__device__ f16 g_ygh[(size_t)BT * DINNER];
__device__ f16 g_h2h[BT * DMODEL];
__device__ f16 g_ffh[(size_t)BT * DFF];
// fp16 weights (hi only)
__device__ f16 g_win[PROJ_OUT * 1024];
__device__ f16 g_wo [1024 * 2048];
__device__ f16 g_w1 [4096 * 1024];
__device__ f16 g_w2 [1024 * 4096];
// fp16 hi/lo split of w_in tail rows (4096..4223) for high-precision scan params
__device__ f16 g_wth[128 * 1024], g_wtl[128 * 1024];

// ---------------- math helpers ----------------
__device__ __forceinline__ float siluf_(float x)    { return x / (1.f + __expf(-x)); }
__device__ __forceinline__ float geluf_(float x) {
    float x3 = x * x * x;
    return 0.5f * x * (1.f + tanhf(0.7978845608028654f * (x + 0.044715f * x3)));
}
__device__ __forceinline__ float sigmoidf_(float x) { return 1.f / (1.f + __expf(-x)); }
__device__ __forceinline__ float softplusf_(float x) {
    return (x > 20.f) ? x : log1pf(expf(x));
}
__device__ __forceinline__ void split1(float v, f16* h, f16* l) {
    f16 hh = __float2half_rn(v);
    *h = hh;
    *l = __float2half_rn(v - __half2float(hh));
}

__device__ __forceinline__ float block_reduce_sum(float v) {
    __shared__ float sh[32];
    int lane = threadIdx.x & 31, wid = threadIdx.x >> 5;
    int nwarps = blockDim.x >> 5;
    #pragma unroll
    for (int m = 16; m > 0; m >>= 1) v += __shfl_xor_sync(0xffffffffu, v, m);
    if (lane == 0) sh[wid] = v;
    __syncthreads();
    if (wid == 0) {
        v = (lane < nwarps) ? sh[lane] : 0.f;
        #pragma unroll
        for (int m = 16; m > 0; m >>= 1) v += __shfl_xor_sync(0xffffffffu, v, m);
        if (lane == 0) sh[0] = v;
    }
    __syncthreads();
    return sh[0];
}

// ---------------- low-level (sm_80-compatible only) ----------------
__device__ __forceinline__ uint32_t smem_u32(const void* p) {
    uint32_t a;
    asm("{ .reg .u64 t; cvta.to.shared.u64 t, %1; cvt.u32.u64 %0, t; }" : "=r"(a) : "l"(p));
    return a;
}
#define CP_ASYNC16(dst, src) \
    asm volatile("cp.async.cg.shared.global [%0], [%1], 16;" :: "r"((uint32_t)(dst)), "l"(src))
#define CP_COMMIT() asm volatile("cp.async.commit_group;" ::: "memory")

__device__ __forceinline__ void ldsm_x4(uint32_t* r, uint32_t addr) {
    asm volatile("ldmatrix.sync.aligned.m8n8.x4.shared.b16 {%0,%1,%2,%3}, [%4];"
                 : "=r"(r[0]), "=r"(r[1]), "=r"(r[2]), "=r"(r[3]) : "r"(addr));
}
__device__ __forceinline__ void ldsm_x2(uint32_t* r, uint32_t addr) {
    asm volatile("ldmatrix.sync.aligned.m8n8.x2.shared.b16 {%0,%1}, [%2];"
                 : "=r"(r[0]), "=r"(r[1]) : "r"(addr));
}
__device__ __forceinline__ void mma16816(float* c, const uint32_t* a, const uint32_t* b) {
    asm volatile("mma.sync.aligned.m16n8k16.row.col.f32.f16.f16.f32 "
                 "{%0,%1,%2,%3}, {%4,%5,%6,%7}, {%8,%9}, {%0,%1,%2,%3};"
                 : "+f"(c[0]), "+f"(c[1]), "+f"(c[2]), "+f"(c[3])
                 : "r"(a[0]), "r"(a[1]), "r"(a[2]), "r"(a[3]), "r"(b[0]), "r"(b[1]));
}

// ---------------- rmsnorm + fp16 (optional lo) (D=1024, 256 thr) ----------------
__global__ void rmsnorm_split_kernel(const float* __restrict__ x, const float* __restrict__ w,
                                     f16* __restrict__ oh, f16* __restrict__ ol) {
    int row = blockIdx.x;
    int i = threadIdx.x;
    const float4* xr = (const float4*)(x + (size_t)row * DMODEL);
    float4 v = xr[i];
    float ss = v.x * v.x + v.y * v.y + v.z * v.z + v.w * v.w;
    ss = block_reduce_sum(ss);
    float inv = rsqrtf(ss / (float)DMODEL + 1e-6f);
    float4 wv = ((const float4*)w)[i];
    float o0 = v.x * inv * wv.x, o1 = v.y * inv * wv.y;
    float o2 = v.z * inv * wv.z, o3 = v.w * inv * wv.w;
    __half2 h0, h1, l0, l1;
    split1(o0, &h0.x, &l0.x); split1(o1, &h0.y, &l0.y);
    split1(o2, &h1.x, &l1.x); split1(o3, &h1.y, &l1.y);
    __half2* ohp = (__half2*)(oh + (size_t)row * DMODEL);
    ohp[2 * i] = h0; ohp[2 * i + 1] = h1;
    if (ol) {
        __half2* olp = (__half2*)(ol + (size_t)row * DMODEL);
        olp[2 * i] = l0; olp[2 * i + 1] = l1;
    }
}

// ---------------- gated rmsnorm -> fp16 hi only (DINNER=2048) ----------------
__global__ void gated_norm_kernel(const float* __restrict__ proj, const float* __restrict__ scan_y,
                                  const float* __restrict__ w, f16* __restrict__ oh) {
    int row = blockIdx.x;
    int tid = threadIdx.x;
    const float4* prow = (const float4*)(proj + (size_t)row * PROJ_OUT);
    const float4* sy = (const float4*)(scan_y + (size_t)row * DINNER);
    float4 tv[2];
    float ss = 0.f;
    #pragma unroll
    for (int q = 0; q < 2; ++q) {
        int i = tid + q * 256;
        float4 g = prow[i];
        float4 s = sy[i];
        float4 t;
        t.x = s.x * siluf_(g.x); t.y = s.y * siluf_(g.y);
        t.z = s.z * siluf_(g.z); t.w = s.w * siluf_(g.w);
        tv[q] = t;
        ss += t.x * t.x + t.y * t.y + t.z * t.z + t.w * t.w;
    }
    ss = block_reduce_sum(ss);
    float inv = rsqrtf(ss / (float)DINNER + 1e-6f);
    __half2* ohp = (__half2*)(oh + (size_t)row * DINNER);
    #pragma unroll
    for (int q = 0; q < 2; ++q) {
        int i = tid + q * 256;
        float4 wv = ((const float4*)w)[i];
        __half2 h0, h1;
        h0.x = __float2half_rn(tv[q].x * inv * wv.x);
        h0.y = __float2half_rn(tv[q].y * inv * wv.y);
        h1.x = __float2half_rn(tv[q].z * inv * wv.z);
        h1.y = __float2half_rn(tv[q].w * inv * wv.w);
        ohp[2 * i] = h0; ohp[2 * i + 1] = h1;
    }
}

// ---------------- fp32 -> fp16 convert (vectorized) ----------------
__global__ void cvt4_kernel(const float4* __restrict__ src, __half2* __restrict__ dst, int n4) {
    int i = blockIdx.x * blockDim.x + threadIdx.x;
    if (i >= n4) return;
    float4 v = src[i];
    __half2 h0, h1;
    h0.x = __float2half_rn(v.x); h0.y = __float2half_rn(v.y);
    h1.x = __float2half_rn(v.z); h1.y = __float2half_rn(v.w);
    dst[2 * i] = h0; dst[2 * i + 1] = h1;
}

// ---------------- fp32 -> fp16 hi/lo split (vectorized) ----------------
__global__ void split4_kernel(const float4* __restrict__ src, __half2* __restrict__ hi,
                              __half2* __restrict__ lo, int n4) {
    int i = blockIdx.x * blockDim.x + threadIdx.x;
    if (i >= n4) return;
    float4 v = src[i];
    __half2 h0, h1, l0, l1;
    split1(v.x, &h0.x, &l0.x); split1(v.y, &h0.y, &l0.y);
    split1(v.z, &h1.x, &l1.x); split1(v.w, &h1.y, &l1.y);
    hi[2 * i] = h0; hi[2 * i + 1] = h1;
    lo[2 * i] = l0; lo[2 * i + 1] = l1;
}

// ---------------- fused conv+silu / params / bcpack (one block per (b,t)) ----------------
__global__ void prep_kernel(const float* __restrict__ proj, const float* __restrict__ conv_w,
                            const float* __restrict__ conv_b, float* __restrict__ value,
                            float* __restrict__ par, float* __restrict__ bcT) {
    int bt = blockIdx.x;
    int t = bt & (TQ - 1);
    int tid = threadIdx.x;
    const float* prow = proj + (size_t)bt * PROJ_OUT;
    #pragma unroll
    for (int i = 0; i < 8; ++i) {
        int c = tid + i * 256;
        float acc = conv_b[c];
        #pragma unroll
        for (int k = 0; k < DCONV; ++k) {
            int ts = t - (DCONV - 1) + k;
            if (ts >= 0)
                acc += prow[(ts - t) * (ptrdiff_t)PROJ_OUT + DINNER + c] * conv_w[c * DCONV + k];
        }
        value[(size_t)bt * DINNER + c] = siluf_(acc);
    }
    if (tid < 32) {
        int h = tid;
        par[((size_t)bt * NHEADS + h) * 2 + 0] = softplusf_(prow[PARAM_OFF + 2 * h]);
        par[((size_t)bt * NHEADS + h) * 2 + 1] = sigmoidf_(prow[PARAM_OFF + 2 * h + 1]);
    } else if (tid >= 64 && tid < 80) {
        int n = tid - 64;
        float4 v;
        v.x = prow[BC_OFF + n];
        v.y = prow[BC_OFF + 16 + n];
        v.z = prow[BC_OFF + 32 + n];
        v.w = prow[BC_OFF + 48 + n];
        ((float4*)bcT)[(size_t)bt * 16 + n] = v;
    }
}

// ---------------- sequential SSM scan ----------------
__global__ void scan_kernel(const float* __restrict__ bcT, const float* __restrict__ par,
                            const float* __restrict__ value, float* __restrict__ scan_y) {
    int blk = blockIdx.x;
    int bh = blk >> 1;
    int b = bh >> 5;
    int h = bh & 31;
    int half = blk & 1;
    int tid = threadIdx.x;
    int p = half * 32 + (tid >> 4);
    int n = tid & 15;
    float S0 = 0.f, S1 = 0.f;
    const size_t rowbase = (size_t)b * TQ;
    const float4* bc4 = (const float4*)bcT;
    const float2* ad2 = (const float2*)par;
    float4 nbc = bc4[rowbase * 16 + n];
    float2 nad = ad2[rowbase * NHEADS + h];
    float  nu  = value[rowbase * DINNER + h * DHEAD + p];
    for (int t = 0; t < TQ; ++t) {
        float4 bcv = nbc; float2 ad = nad; float u = nu;
        if (t + 1 < TQ) {
            size_t r2 = rowbase + t + 1;
            nbc = bc4[r2 * 16 + n];
            nad = ad2[r2 * NHEADS + h];
            nu  = value[r2 * DINNER + h * DHEAD + p];
        }
        float A = ad.x, dt = ad.y;
        float dtA = dt * A;
        float du = dt * u;
        float s0n = fmaf(-dtA, S1, fmaf(bcv.x, du, S0));
        float s1n = fmaf(dt, S0, fmaf(1.f - dt * dtA, S1, dt * bcv.y * du));
        S0 = s0n; S1 = s1n;
        float y = bcv.z * s0n + bcv.w * s1n;
        y += __shfl_xor_sync(0xffffffffu, y, 8);
        y += __shfl_xor_sync(0xffffffffu, y, 4);
        y += __shfl_xor_sync(0xffffffffu, y, 2);
        y += __shfl_xor_sync(0xffffffffu, y, 1);
        if (n == 0) scan_y[(rowbase + t) * DINNER + h * DHEAD + p] = y;
    }
}

#define TILEB 10240                 // 128 rows x 80B

// ---------------- fp16 2-product GEMM: 3-stage, single sync per chunk ----------------
#define STAGEB2 (3 * TILEB)
#define GEMM2_SMEM (3 * STAGEB2)    // 92160
__global__ void __launch_bounds__(256, 2)
gemm_mma2(const f16* __restrict__ Ah, const f16* __restrict__ Al,
          const f16* __restrict__ Bh,
          float* __restrict__ C, int N, int K) {
    extern __shared__ __align__(16) f16 dsm[];
    const uint32_t s0 = smem_u32(dsm);
    const int tid = threadIdx.x, wid = tid >> 5, lane = tid & 31;
    const int row0 = blockIdx.y * 128, col0 = blockIdx.x * 128;
    const int wm = wid & 1, wn = wid >> 1;
    const int nch = K >> 5;

    float acc[4][4][4];
    #pragma unroll
    for (int mt = 0; mt < 4; ++mt)
        #pragma unroll
        for (int nt = 0; nt < 4; ++nt)
            #pragma unroll
            for (int q = 0; q < 4; ++q) acc[mt][nt][q] = 0.f;

    const int lr = tid >> 2, lc = tid & 3;
    const f16* gAh = Ah + (size_t)(row0 + lr) * K + lc * 8;
    const f16* gAl = Al + (size_t)(row0 + lr) * K + lc * 8;
    const f16* gBh = Bh + (size_t)(col0 + lr) * K + lc * 8;
    const uint32_t dst = lr * 80 + lc * 16;

    #define LOAD_CHUNK2(stg, k0) do {                                                  \
        uint32_t _b = s0 + (stg) * STAGEB2 + dst;                                      \
        CP_ASYNC16(_b,                       gAh + (k0));                              \
        CP_ASYNC16(_b + 64 * 80,             gAh + (size_t)64 * K + (k0));             \
        CP_ASYNC16(_b + TILEB,               gAl + (k0));                              \
        CP_ASYNC16(_b + TILEB + 64 * 80,     gAl + (size_t)64 * K + (k0));             \
        CP_ASYNC16(_b + 2 * TILEB,           gBh + (k0));                              \
        CP_ASYNC16(_b + 2 * TILEB + 64 * 80, gBh + (size_t)64 * K + (k0));             \
        CP_COMMIT();                                                                   \
    } while (0)

    LOAD_CHUNK2(0, 0);
    LOAD_CHUNK2(1, 32);

    const uint32_t a_row = (uint32_t)(wm * 64 + (lane & 15));
    const uint32_t a_coff = (uint32_t)((lane >> 4) * 8);
    const uint32_t b_row2 = (uint32_t)(wn * 32 + (lane & 7) + (((lane >> 4) & 1) << 3));
    const uint32_t b_coff = (uint32_t)(((lane >> 3) & 1) * 8);

    for (int ch = 0; ch < nch; ++ch) {
        if (ch + 1 < nch)
            asm volatile("cp.async.wait_group 1;" ::: "memory");
        else
            asm volatile("cp.async.wait_group 0;" ::: "memory");
        __syncthreads();
        if (ch + 2 < nch)
            LOAD_CHUNK2((ch + 2) % 3, (ch + 2) << 5);

        const uint32_t sb = s0 + (ch % 3) * STAGEB2;
        const uint32_t sAh_ = sb, sAl_ = sb + TILEB, sBh_ = sb + 2 * TILEB;
        #pragma unroll
        for (int ks = 0; ks < 2; ++ks) {
            const uint32_t acol = (ks * 16 + a_coff) * 2;
            const uint32_t bcol = (ks * 16 + b_coff) * 2;
            uint32_t afr[4][4], bfr[4][2];
            #pragma unroll
            for (int q = 0; q < 2; ++q) {
                uint32_t tmp[4];
                ldsm_x4(tmp, sBh_ + (b_row2 + q * 16) * 80 + bcol);
                bfr[2 * q][0] = tmp[0]; bfr[2 * q][1] = tmp[1];
                bfr[2 * q + 1][0] = tmp[2]; bfr[2 * q + 1][1] = tmp[3];
            }
            #pragma unroll
            for (int mt = 0; mt < 4; ++mt)
                ldsm_x4(afr[mt], sAh_ + (a_row + mt * 16) * 80 + acol);
            #pragma unroll
            for (int mt = 0; mt < 4; ++mt)
                #pragma unroll
                for (int nt = 0; nt < 4; ++nt)
                    mma16816(acc[mt][nt], afr[mt], bfr[nt]);
            #pragma unroll
            for (int mt = 0; mt < 4; ++mt)
                ldsm_x4(afr[mt], sAl_ + (a_row + mt * 16) * 80 + acol);
            #pragma unroll
            for (int mt = 0; mt < 4; ++mt)
                #pragma unroll
                for (int nt = 0; nt < 4; ++nt)
                    mma16816(acc[mt][nt], afr[mt], bfr[nt]);
        }
    }

    const int er = lane >> 2, ec = (lane & 3) << 1;
    #pragma unroll
    for (int mt = 0; mt < 4; ++mt) {
        #pragma unroll
        for (int nt = 0; nt < 4; ++nt) {
            int gr = row0 + wm * 64 + mt * 16 + er;
            int gc = col0 + wn * 32 + nt * 8 + ec;
            const float* cc = acc[mt][nt];
            #pragma unroll
            for (int half = 0; half < 2; ++half) {
                int r = gr + half * 8;
                float2 v; v.x = cc[half * 2 + 0]; v.y = cc[half * 2 + 1];
                *(float2*)(C + (size_t)r * N + gc) = v;
            }
        }
    }
}

// ---------------- fp16 1-product GEMM: 3-stage, single sync per chunk ----------------
// mode 1: C = acc + bias? + res? (fp32) ; mode 2: Oh = fp16(gelu(acc + bias))
#define STAGEB1 (2 * TILEB)
#define GEMM1_SMEM (3 * STAGEB1)    // 61440
__global__ void __launch_bounds__(256, 2)
gemm_mma1(const f16* __restrict__ Ah, const f16* __restrict__ Bh,
          const float* __restrict__ bias, const float* __restrict__ res,
          float* __restrict__ C, f16* __restrict__ Oh,
          int N, int K, int mode) {
    extern __shared__ __align__(16) f16 dsm[];
    const uint32_t s0 = smem_u32(dsm);
    const int tid = threadIdx.x, wid = tid >> 5, lane = tid & 31;
    const int row0 = blockIdx.y * 128, col0 = blockIdx.x * 128;
    const int wm = wid & 1, wn = wid >> 1;
    const int nch = K >> 5;

    float acc[4][4][4];
    #pragma unroll
    for (int mt = 0; mt < 4; ++mt)
        #pragma unroll
        for (int nt = 0; nt < 4; ++nt)
            #pragma unroll
            for (int q = 0; q < 4; ++q) acc[mt][nt][q] = 0.f;

    const int lr = tid >> 2, lc = tid & 3;
    const f16* gAh = Ah + (size_t)(row0 + lr) * K + lc * 8;
    const f16* gBh = Bh + (size_t)(col0 + lr) * K + lc * 8;
    const uint32_t dst = lr * 80 + lc * 16;

    #define LOAD_CHUNK1(stg, k0) do {                                                  \
        uint32_t _b = s0 + (stg) * STAGEB1 + dst;                                      \
        CP_ASYNC16(_b,                   gAh + (k0));                                  \
        CP_ASYNC16(_b + 64 * 80,         gAh + (size_t)64 * K + (k0));                 \
        CP_ASYNC16(_b + TILEB,           gBh + (k0));                                  \
        CP_ASYNC16(_b + TILEB + 64 * 80, gBh + (size_t)64 * K + (k0));                 \
        CP_COMMIT();                                                                   \
    } while (0)

    LOAD_CHUNK1(0, 0);
    LOAD_CHUNK1(1, 32);

    const uint32_t a_row = (uint32_t)(wm * 64 + (lane & 15));
    const uint32_t a_coff = (uint32_t)((lane >> 4) * 8);
    const uint32_t b_row2 = (uint32_t)(wn * 32 + (lane & 7) + (((lane >> 4) & 1) << 3));
    const uint32_t b_coff = (uint32_t)(((lane >> 3) & 1) * 8);

    for (int ch = 0; ch < nch; ++ch) {
        if (ch + 1 < nch)
            asm volatile("cp.async.wait_group 1;" ::: "memory");
        else
            asm volatile("cp.async.wait_group 0;" ::: "memory");
        __syncthreads();
        if (ch + 2 < nch)
            LOAD_CHUNK1((ch + 2) % 3, (ch + 2) << 5);

        const uint32_t sb = s0 + (ch % 3) * STAGEB1;
        const uint32_t sAh_ = sb, sBh_ = sb + TILEB;
        #pragma unroll
        for (int ks = 0; ks < 2; ++ks) {
            const uint32_t acol = (ks * 16 + a_coff) * 2;
            const uint32_t bcol = (ks * 16 + b_coff) * 2;
            uint32_t afr[4][4], bfr[4][2];
            #pragma unroll
            for (int q = 0; q < 2; ++q) {
                uint32_t tmp[4];
                ldsm_x4(tmp, sBh_ + (b_row2 + q * 16) * 80 + bcol);
                bfr[2 * q][0] = tmp[0]; bfr[2 * q][1] = tmp[1];
                bfr[2 * q + 1][0] = tmp[2]; bfr[2 * q + 1][1] = tmp[3];
            }
            #pragma unroll
            for (int mt = 0; mt < 4; ++mt)
                ldsm_x4(afr[mt], sAh_ + (a_row + mt * 16) * 80 + acol);
            #pragma unroll
            for (int mt = 0; mt < 4; ++mt)
                #pragma unroll
                for (int nt = 0; nt < 4; ++nt)
                    mma16816(acc[mt][nt], afr[mt], bfr[nt]);
        }
    }

    const int er = lane >> 2, ec = (lane & 3) << 1;
    #pragma unroll
    for (int mt = 0; mt < 4; ++mt) {
        #pragma unroll
        for (int nt = 0; nt < 4; ++nt) {
            int gr = row0 + wm * 64 + mt * 16 + er;
            int gc = col0 + wn * 32 + nt * 8 + ec;
            const float* cc = acc[mt][nt];
            #pragma unroll
            for (int half = 0; half < 2; ++half) {
                int r = gr + half * 8;
                float v0 = cc[half * 2 + 0], v1 = cc[half * 2 + 1];
                if (mode == 2) {
                    v0 = geluf_(v0 + bias[gc]);
                    v1 = geluf_(v1 + bias[gc + 1]);
                    __half2 hp;
                    hp.x = __float2half_rn(v0);
                    hp.y = __float2half_rn(v1);
                    *(__half2*)(Oh + (size_t)r * N + gc) = hp;
                } else {
                    if (bias) { v0 += bias[gc]; v1 += bias[gc + 1]; }
                    if (res) {
                        const float* rp = res + (size_t)r * N + gc;
                        v0 += rp[0]; v1 += rp[1];
                    }
                    float2 v; v.x = v0; v.y = v1;
                    *(float2*)(C + (size_t)r * N + gc) = v;
                }
            }
        }
    }
}

// ---------------- fp16 3-product GEMM (high precision; in-proj tail) ----------------
#define STAGEB3 (4 * TILEB)
#define GEMM3_SMEM (2 * STAGEB3)
__global__ void __launch_bounds__(256, 2)
gemm_mma3(const f16* __restrict__ Ah, const f16* __restrict__ Al,
          const f16* __restrict__ Bh, const f16* __restrict__ Bl,
          float* __restrict__ C, int ldN, int K) {
    extern __shared__ __align__(16) f16 dsm[];
    const uint32_t s0 = smem_u32(dsm);
    const int tid = threadIdx.x, wid = tid >> 5, lane = tid & 31;
    const int row0 = blockIdx.y * 128, col0 = blockIdx.x * 128;
    const int wm = wid & 1, wn = wid >> 1;
    const int nch = K >> 5;

    float acc[4][4][4];
    #pragma unroll
    for (int mt = 0; mt < 4; ++mt)
        #pragma unroll
        for (int nt = 0; nt < 4; ++nt)
            #pragma unroll
            for (int q = 0; q < 4; ++q) acc[mt][nt][q] = 0.f;

    const int lr = tid >> 2, lc = tid & 3;
    const f16* gAh = Ah + (size_t)(row0 + lr) * K + lc * 8;
    const f16* gAl = Al + (size_t)(row0 + lr) * K + lc * 8;
    const f16* gBh = Bh + (size_t)(col0 + lr) * K + lc * 8;
    const f16* gBl = Bl + (size_t)(col0 + lr) * K + lc * 8;
    const uint32_t dst = lr * 80 + lc * 16;

    #define LOAD_CHUNK3(stg, k0) do {                                                  \
        uint32_t _b = s0 + (stg) * STAGEB3 + dst;                                      \
        CP_ASYNC16(_b,                       gAh + (k0));                              \
        CP_ASYNC16(_b + 64 * 80,             gAh + (size_t)64 * K + (k0));             \
        CP_ASYNC16(_b + TILEB,               gAl + (k0));                              \
        CP_ASYNC16(_b + TILEB + 64 * 80,     gAl + (size_t)64 * K + (k0));             \
        CP_ASYNC16(_b + 2 * TILEB,           gBh + (k0));                              \
        CP_ASYNC16(_b + 2 * TILEB + 64 * 80, gBh + (size_t)64 * K + (k0));             \
        CP_ASYNC16(_b + 3 * TILEB,           gBl + (k0));                              \
        CP_ASYNC16(_b + 3 * TILEB + 64 * 80, gBl + (size_t)64 * K + (k0));             \
        CP_COMMIT();                                                                   \
    } while (0)

    LOAD_CHUNK3(0, 0);

    const uint32_t a_row = (uint32_t)(wm * 64 + (lane & 15));
    const uint32_t a_coff = (uint32_t)((lane >> 4) * 8);
    const uint32_t b_row = (uint32_t)(wn * 32 + (lane & 7));
    const uint32_t b_coff = (uint32_t)(((lane >> 3) & 1) * 8);

    for (int ch = 0; ch < nch; ++ch) {
        const int stg = ch & 1;
        if (ch + 1 < nch) {
            LOAD_CHUNK3(stg ^ 1, (ch + 1) << 5);
            asm volatile("cp.async.wait_group 1;" ::: "memory");
        } else {
            asm volatile("cp.async.wait_group 0;" ::: "memory");
        }
        __syncthreads();

        const uint32_t sb = s0 + stg * STAGEB3;
        const uint32_t sAh_ = sb, sAl_ = sb + TILEB, sBh_ = sb + 2 * TILEB, sBl_ = sb + 3 * TILEB;
        #pragma unroll
        for (int ks = 0; ks < 2; ++ks) {
            const uint32_t acol = (ks * 16 + a_coff) * 2;
            const uint32_t bcol = (ks * 16 + b_coff) * 2;
            uint32_t afr[4][4], bh_[4][2], bl_[4][2];
            #pragma unroll
            for (int nt = 0; nt < 4; ++nt) {
                ldsm_x2(bh_[nt], sBh_ + (b_row + nt * 8) * 80 + bcol);
                ldsm_x2(bl_[nt], sBl_ + (b_row + nt * 8) * 80 + bcol);
            }
            #pragma unroll
            for (int mt = 0; mt < 4; ++mt)
                ldsm_x4(afr[mt], sAh_ + (a_row + mt * 16) * 80 + acol);
            #pragma unroll
            for (int mt = 0; mt < 4; ++mt)
                #pragma unroll
                for (int nt = 0; nt < 4; ++nt) {
                    mma16816(acc[mt][nt], afr[mt], bh_[nt]);
                    mma16816(acc[mt][nt], afr[mt], bl_[nt]);
                }
            #pragma unroll
            for (int mt = 0; mt < 4; ++mt)
                ldsm_x4(afr[mt], sAl_ + (a_row + mt * 16) * 80 + acol);
            #pragma unroll
            for (int mt = 0; mt < 4; ++mt)
                #pragma unroll
                for (int nt = 0; nt < 4; ++nt)
                    mma16816(acc[mt][nt], afr[mt], bh_[nt]);
        }
        __syncthreads();
    }

    const int er = lane >> 2, ec = (lane & 3) << 1;
    #pragma unroll
    for (int mt = 0; mt < 4; ++mt) {
        #pragma unroll
        for (int nt = 0; nt < 4; ++nt) {
            int gr = row0 + wm * 64 + mt * 16 + er;
            int gc = col0 + wn * 32 + nt * 8 + ec;
            const float* cc = acc[mt][nt];
            #pragma unroll
            for (int half = 0; half < 2; ++half) {
                int r = gr + half * 8;
                float2 v; v.x = cc[half * 2 + 0]; v.y = cc[half * 2 + 1];
                *(float2*)(C + (size_t)r * ldN + gc) = v;
            }
        }
    }
}

// ---------------- launch ----------------
extern "C" void kernel_launch(void* const* d_in, const int* in_sizes, int n_in,
                              void* d_out, int out_size) {
    const float* x       = (const float*)d_in[0];
    const float* w_in    = (const float*)d_in[1];
    const float* conv_w  = (const float*)d_in[2];
    const float* conv_b  = (const float*)d_in[3];
    const float* norm1_w = (const float*)d_in[4];
    const float* out_nw  = (const float*)d_in[5];
    const float* w_out   = (const float*)d_in[6];
    const float* norm2_w = (const float*)d_in[7];
    const float* ff_w1   = (const float*)d_in[8];
    const float* ff_b1   = (const float*)d_in[9];
    const float* ff_w2   = (const float*)d_in[10];
    const float* ff_b2   = (const float*)d_in[11];
    float* out = (float*)d_out;

    float *proj, *val, *par, *bcT, *scan, *x1;
    f16 *h1h, *h1l, *ygh, *h2h, *ffh;
    f16 *win, *wo, *w1, *w2, *wth, *wtl;
    cudaGetSymbolAddress((void**)&proj, g_proj);
    cudaGetSymbolAddress((void**)&val,  g_val);
    cudaGetSymbolAddress((void**)&par,  g_par);
    cudaGetSymbolAddress((void**)&bcT,  g_bcT);
    cudaGetSymbolAddress((void**)&scan, g_scan);
    cudaGetSymbolAddress((void**)&x1,   g_x1);
    cudaGetSymbolAddress((void**)&h1h,  g_h1h);  cudaGetSymbolAddress((void**)&h1l, g_h1l);
    cudaGetSymbolAddress((void**)&ygh,  g_ygh);
    cudaGetSymbolAddress((void**)&h2h,  g_h2h);
    cudaGetSymbolAddress((void**)&ffh,  g_ffh);
    cudaGetSymbolAddress((void**)&win,  g_win);
    cudaGetSymbolAddress((void**)&wo,   g_wo);
    cudaGetSymbolAddress((void**)&w1,   g_w1);
    cudaGetSymbolAddress((void**)&w2,   g_w2);
    cudaGetSymbolAddress((void**)&wth,  g_wth);
    cudaGetSymbolAddress((void**)&wtl,  g_wtl);

    cudaFuncSetAttribute(gemm_mma2, cudaFuncAttributeMaxDynamicSharedMemorySize, GEMM2_SMEM);
    cudaFuncSetAttribute(gemm_mma1, cudaFuncAttributeMaxDynamicSharedMemorySize, GEMM1_SMEM);
    cudaFuncSetAttribute(gemm_mma3, cudaFuncAttributeMaxDynamicSharedMemorySize, GEMM3_SMEM);

    // weight fp16 conversion (idempotent)
    cvt4_kernel<<<(PROJ_OUT * 1024 / 4 + 255) / 256, 256>>>((const float4*)w_in,
        (__half2*)win, PROJ_OUT * 1024 / 4);
    cvt4_kernel<<<(1024 * 2048 / 4 + 255) / 256, 256>>>((const float4*)w_out,
        (__half2*)wo, 1024 * 2048 / 4);
    cvt4_kernel<<<(4096 * 1024 / 4 + 255) / 256, 256>>>((const float4*)ff_w1,
        (__half2*)w1, 4096 * 1024 / 4);
    cvt4_kernel<<<(1024 * 4096 / 4 + 255) / 256, 256>>>((const float4*)ff_w2,
        (__half2*)w2, 1024 * 4096 / 4);
    // hi/lo split of w_in tail rows (scan-parameter columns)
    split4_kernel<<<(128 * 1024 / 4 + 255) / 256, 256>>>(
        (const float4*)(w_in + (size_t)4096 * 1024), (__half2*)wth, (__half2*)wtl, 128 * 1024 / 4);

    // 1. h1 = rmsnorm(x) (fp16 hi+lo)
    rmsnorm_split_kernel<<<BT, 256>>>(x, norm1_w, h1h, h1l);
    // 2a. proj[:, :4096] = h1 @ w_in[:4096]^T  (2-product)
    gemm_mma2<<<dim3(32, BT / 128), 256, GEMM2_SMEM>>>(h1h, h1l, win, proj, PROJ_OUT, DMODEL);
    // 2b. proj[:, 4096:] = h1 @ w_in[4096:]^T  (3-product, scan params)
    gemm_mma3<<<dim3(1, BT / 128), 256, GEMM3_SMEM>>>(h1h, h1l, wth, wtl,
                                                      proj + 4096, PROJ_OUT, DMODEL);
    // 3. fused conv+silu / params / bcpack
    prep_kernel<<<BT, 256>>>(proj, conv_w, conv_b, val, par, bcT);
    // 4. scan
    scan_kernel<<<2 * BQ * NHEADS, 512>>>(bcT, par, val, scan);
    // 5. yg = rmsnorm(scan * silu(gate)) (fp16 hi only)
    gated_norm_kernel<<<BT, 256>>>(proj, scan, out_nw, ygh);
    // 6. x1 = x + yg @ w_out^T  (1-product)
    gemm_mma1<<<dim3(DMODEL / 128, BT / 128), 256, GEMM1_SMEM>>>(ygh, wo, nullptr, x,
                                                    x1, nullptr, DMODEL, DINNER, 1);
    // 7. h2 = rmsnorm(x1) (fp16 hi only)
    rmsnorm_split_kernel<<<BT, 256>>>(x1, norm2_w, h2h, nullptr);
    // 8. ffh = fp16(gelu(h2 @ ff_w1^T + b1))  (1-product)
    gemm_mma1<<<dim3(DFF / 128, BT / 128), 256, GEMM1_SMEM>>>(h2h, w1, ff_b1, nullptr,
                                                 nullptr, ffh, DFF, DMODEL, 2);
    // 9. out = x1 + ffh @ ff_w2^T + b2  (1-product)
    gemm_mma1<<<dim3(DMODEL / 128, BT / 128), 256, GEMM1_SMEM>>>(ffh, w2, ff_b2, x1,
                                                    out, nullptr, DMODEL, DFF, 1);
}

// round 14
// speedup vs baseline: 3.3816x; 1.0927x over previous
#include <cuda_runtime.h>
#include <cuda_fp16.h>
#include <math.h>
#include <stdint.h>

typedef __half f16;

#define BQ 2
#define TQ 2048
#define DMODEL 1024
#define DINNER 2048
#define NHEADS 32
#define DHEAD 64
#define DCONV 4
#define PROJ_OUT 4224
#define BT 4096
#define PARAM_OFF 4096
#define BC_OFF 4160
#define DFF 4096

// ---------------- scratch (device globals; no allocation) ----------------
__device__ float g_proj[(size_t)BT * PROJ_OUT];
__device__ float g_val [(size_t)BT * DINNER];
__device__ float g_par [(size_t)BT * NHEADS * 2];
__device__ float g_bcT [(size_t)BT * 64];
__device__ float g_scan[(size_t)BT * DINNER];
__device__ float g_x1  [BT * DMODEL];
// fp16 activations
__device__ f16 g_h1h[BT * DMODEL],         g_h1l[BT * DMODEL];
__device__ f16 g_ygh[(size_t)BT * DINNER];
__device__ f16 g_h2h[BT * DMODEL];
__device__ f16 g_ffh[(size_t)BT * DFF];
// fp16 weights (hi only)
__device__ f16 g_win[PROJ_OUT * 1024];
__device__ f16 g_wo [1024 * 2048];
__device__ f16 g_w1 [4096 * 1024];
__device__ f16 g_w2 [1024 * 4096];
// fp16 hi/lo split of w_in tail rows (4096..4223) for high-precision scan params
__device__ f16 g_wth[128 * 1024], g_wtl[128 * 1024];

// ---------------- math helpers ----------------
__device__ __forceinline__ float siluf_(float x)    { return x / (1.f + __expf(-x)); }
__device__ __forceinline__ float geluf_(float x) {
    float x3 = x * x * x;
    return 0.5f * x * (1.f + tanhf(0.7978845608028654f * (x + 0.044715f * x3)));
}
__device__ __forceinline__ float sigmoidf_(float x) { return 1.f / (1.f + __expf(-x)); }
__device__ __forceinline__ float softplusf_(float x) {
    return (x > 20.f) ? x : log1pf(expf(x));
}
__device__ __forceinline__ void split1(float v, f16* h, f16* l) {
    f16 hh = __float2half_rn(v);
    *h = hh;
    *l = __float2half_rn(v - __half2float(hh));
}

__device__ __forceinline__ float block_reduce_sum(float v) {
    __shared__ float sh[32];
    int lane = threadIdx.x & 31, wid = threadIdx.x >> 5;
    int nwarps = blockDim.x >> 5;
    #pragma unroll
    for (int m = 16; m > 0; m >>= 1) v += __shfl_xor_sync(0xffffffffu, v, m);
    if (lane == 0) sh[wid] = v;
    __syncthreads();
    if (wid == 0) {
        v = (lane < nwarps) ? sh[lane] : 0.f;
        #pragma unroll
        for (int m = 16; m > 0; m >>= 1) v += __shfl_xor_sync(0xffffffffu, v, m);
        if (lane == 0) sh[0] = v;
    }
    __syncthreads();
    return sh[0];
}

// ---------------- low-level (sm_80-compatible only) ----------------
__device__ __forceinline__ uint32_t smem_u32(const void* p) {
    uint32_t a;
    asm("{ .reg .u64 t; cvta.to.shared.u64 t, %1; cvt.u32.u64 %0, t; }" : "=r"(a) : "l"(p));
    return a;
}
#define CP_ASYNC16(dst, src) \
    asm volatile("cp.async.cg.shared.global [%0], [%1], 16;" :: "r"((uint32_t)(dst)), "l"(src))
#define CP_COMMIT() asm volatile("cp.async.commit_group;" ::: "memory")

__device__ __forceinline__ void ldsm_x4(uint32_t* r, uint32_t addr) {
    asm volatile("ldmatrix.sync.aligned.m8n8.x4.shared.b16 {%0,%1,%2,%3}, [%4];"
                 : "=r"(r[0]), "=r"(r[1]), "=r"(r[2]), "=r"(r[3]) : "r"(addr));
}
__device__ __forceinline__ void ldsm_x2(uint32_t* r, uint32_t addr) {
    asm volatile("ldmatrix.sync.aligned.m8n8.x2.shared.b16 {%0,%1}, [%2];"
                 : "=r"(r[0]), "=r"(r[1]) : "r"(addr));
}
__device__ __forceinline__ void mma16816(float* c, const uint32_t* a, const uint32_t* b) {
    asm volatile("mma.sync.aligned.m16n8k16.row.col.f32.f16.f16.f32 "
                 "{%0,%1,%2,%3}, {%4,%5,%6,%7}, {%8,%9}, {%0,%1,%2,%3};"
                 : "+f"(c[0]), "+f"(c[1]), "+f"(c[2]), "+f"(c[3])
                 : "r"(a[0]), "r"(a[1]), "r"(a[2]), "r"(a[3]), "r"(b[0]), "r"(b[1]));
}

// ---------------- rmsnorm + fp16 (optional lo) (D=1024, 256 thr) ----------------
__global__ void rmsnorm_split_kernel(const float* __restrict__ x, const float* __restrict__ w,
                                     f16* __restrict__ oh, f16* __restrict__ ol) {
    int row = blockIdx.x;
    int i = threadIdx.x;
    const float4* xr = (const float4*)(x + (size_t)row * DMODEL);
    float4 v = xr[i];
    float ss = v.x * v.x + v.y * v.y + v.z * v.z + v.w * v.w;
    ss = block_reduce_sum(ss);
    float inv = rsqrtf(ss / (float)DMODEL + 1e-6f);
    float4 wv = ((const float4*)w)[i];
    float o0 = v.x * inv * wv.x, o1 = v.y * inv * wv.y;
    float o2 = v.z * inv * wv.z, o3 = v.w * inv * wv.w;
    __half2 h0, h1, l0, l1;
    split1(o0, &h0.x, &l0.x); split1(o1, &h0.y, &l0.y);
    split1(o2, &h1.x, &l1.x); split1(o3, &h1.y, &l1.y);
    __half2* ohp = (__half2*)(oh + (size_t)row * DMODEL);
    ohp[2 * i] = h0; ohp[2 * i + 1] = h1;
    if (ol) {
        __half2* olp = (__half2*)(ol + (size_t)row * DMODEL);
        olp[2 * i] = l0; olp[2 * i + 1] = l1;
    }
}

// ---------------- gated rmsnorm -> fp16 hi only (DINNER=2048) ----------------
__global__ void gated_norm_kernel(const float* __restrict__ proj, const float* __restrict__ scan_y,
                                  const float* __restrict__ w, f16* __restrict__ oh) {
    int row = blockIdx.x;
    int tid = threadIdx.x;
    const float4* prow = (const float4*)(proj + (size_t)row * PROJ_OUT);
    const float4* sy = (const float4*)(scan_y + (size_t)row * DINNER);
    float4 tv[2];
    float ss = 0.f;
    #pragma unroll
    for (int q = 0; q < 2; ++q) {
        int i = tid + q * 256;
        float4 g = prow[i];
        float4 s = sy[i];
        float4 t;
        t.x = s.x * siluf_(g.x); t.y = s.y * siluf_(g.y);
        t.z = s.z * siluf_(g.z); t.w = s.w * siluf_(g.w);
        tv[q] = t;
        ss += t.x * t.x + t.y * t.y + t.z * t.z + t.w * t.w;
    }
    ss = block_reduce_sum(ss);
    float inv = rsqrtf(ss / (float)DINNER + 1e-6f);
    __half2* ohp = (__half2*)(oh + (size_t)row * DINNER);
    #pragma unroll
    for (int q = 0; q < 2; ++q) {
        int i = tid + q * 256;
        float4 wv = ((const float4*)w)[i];
        __half2 h0, h1;
        h0.x = __float2half_rn(tv[q].x * inv * wv.x);
        h0.y = __float2half_rn(tv[q].y * inv * wv.y);
        h1.x = __float2half_rn(tv[q].z * inv * wv.z);
        h1.y = __float2half_rn(tv[q].w * inv * wv.w);
        ohp[2 * i] = h0; ohp[2 * i + 1] = h1;
    }
}

// ---------------- fp32 -> fp16 convert (vectorized) ----------------
__global__ void cvt4_kernel(const float4* __restrict__ src, __half2* __restrict__ dst, int n4) {
    int i = blockIdx.x * blockDim.x + threadIdx.x;
    if (i >= n4) return;
    float4 v = src[i];
    __half2 h0, h1;
    h0.x = __float2half_rn(v.x); h0.y = __float2half_rn(v.y);
    h1.x = __float2half_rn(v.z); h1.y = __float2half_rn(v.w);
    dst[2 * i] = h0; dst[2 * i + 1] = h1;
}

// ---------------- fp32 -> fp16 hi/lo split (vectorized) ----------------
__global__ void split4_kernel(const float4* __restrict__ src, __half2* __restrict__ hi,
                              __half2* __restrict__ lo, int n4) {
    int i = blockIdx.x * blockDim.x + threadIdx.x;
    if (i >= n4) return;
    float4 v = src[i];
    __half2 h0, h1, l0, l1;
    split1(v.x, &h0.x, &l0.x); split1(v.y, &h0.y, &l0.y);
    split1(v.z, &h1.x, &l1.x); split1(v.w, &h1.y, &l1.y);
    hi[2 * i] = h0; hi[2 * i + 1] = h1;
    lo[2 * i] = l0; lo[2 * i + 1] = l1;
}

// ---------------- fused conv+silu / params / bcpack (one block per (b,t)) ----------------
__global__ void prep_kernel(const float* __restrict__ proj, const float* __restrict__ conv_w,
                            const float* __restrict__ conv_b, float* __restrict__ value,
                            float* __restrict__ par, float* __restrict__ bcT) {
    int bt = blockIdx.x;
    int t = bt & (TQ - 1);
    int tid = threadIdx.x;
    const float* prow = proj + (size_t)bt * PROJ_OUT;
    #pragma unroll
    for (int i = 0; i < 8; ++i) {
        int c = tid + i * 256;
        float acc = conv_b[c];
        #pragma unroll
        for (int k = 0; k < DCONV; ++k) {
            int ts = t - (DCONV - 1) + k;
            if (ts >= 0)
                acc += prow[(ts - t) * (ptrdiff_t)PROJ_OUT + DINNER + c] * conv_w[c * DCONV + k];
        }
        value[(size_t)bt * DINNER + c] = siluf_(acc);
    }
    if (tid < 32) {
        int h = tid;
        par[((size_t)bt * NHEADS + h) * 2 + 0] = softplusf_(prow[PARAM_OFF + 2 * h]);
        par[((size_t)bt * NHEADS + h) * 2 + 1] = sigmoidf_(prow[PARAM_OFF + 2 * h + 1]);
    } else if (tid >= 64 && tid < 80) {
        int n = tid - 64;
        float4 v;
        v.x = prow[BC_OFF + n];
        v.y = prow[BC_OFF + 16 + n];
        v.z = prow[BC_OFF + 32 + n];
        v.w = prow[BC_OFF + 48 + n];
        ((float4*)bcT)[(size_t)bt * 16 + n] = v;
    }
}

// ---------------- sequential SSM scan ----------------
__global__ void scan_kernel(const float* __restrict__ bcT, const float* __restrict__ par,
                            const float* __restrict__ value, float* __restrict__ scan_y) {
    int blk = blockIdx.x;
    int bh = blk >> 1;
    int b = bh >> 5;
    int h = bh & 31;
    int half = blk & 1;
    int tid = threadIdx.x;
    int p = half * 32 + (tid >> 4);
    int n = tid & 15;
    float S0 = 0.f, S1 = 0.f;
    const size_t rowbase = (size_t)b * TQ;
    const float4* bc4 = (const float4*)bcT;
    const float2* ad2 = (const float2*)par;
    float4 nbc = bc4[rowbase * 16 + n];
    float2 nad = ad2[rowbase * NHEADS + h];
    float  nu  = value[rowbase * DINNER + h * DHEAD + p];
    for (int t = 0; t < TQ; ++t) {
        float4 bcv = nbc; float2 ad = nad; float u = nu;
        if (t + 1 < TQ) {
            size_t r2 = rowbase + t + 1;
            nbc = bc4[r2 * 16 + n];
            nad = ad2[r2 * NHEADS + h];
            nu  = value[r2 * DINNER + h * DHEAD + p];
        }
        float A = ad.x, dt = ad.y;
        float dtA = dt * A;
        float du = dt * u;
        float s0n = fmaf(-dtA, S1, fmaf(bcv.x, du, S0));
        float s1n = fmaf(dt, S0, fmaf(1.f - dt * dtA, S1, dt * bcv.y * du));
        S0 = s0n; S1 = s1n;
        float y = bcv.z * s0n + bcv.w * s1n;
        y += __shfl_xor_sync(0xffffffffu, y, 8);
        y += __shfl_xor_sync(0xffffffffu, y, 4);
        y += __shfl_xor_sync(0xffffffffu, y, 2);
        y += __shfl_xor_sync(0xffffffffu, y, 1);
        if (n == 0) scan_y[(rowbase + t) * DINNER + h * DHEAD + p] = y;
    }
}

#define TILEB 10240                 // 128 rows x 80B

// ---------------- fp16 1-product GEMM: 3-stage, single sync per chunk ----------------
// mode 1: C = acc + bias? + res? (fp32) ; mode 2: Oh = fp16(gelu(acc + bias))
#define STAGEB1 (2 * TILEB)
#define GEMM1_SMEM (3 * STAGEB1)    // 61440
__global__ void __launch_bounds__(256, 2)
gemm_mma1(const f16* __restrict__ Ah, const f16* __restrict__ Bh,
          const float* __restrict__ bias, const float* __restrict__ res,
          float* __restrict__ C, f16* __restrict__ Oh,
          int N, int K, int mode) {
    extern __shared__ __align__(16) f16 dsm[];
    const uint32_t s0 = smem_u32(dsm);
    const int tid = threadIdx.x, wid = tid >> 5, lane = tid & 31;
    const int row0 = blockIdx.y * 128, col0 = blockIdx.x * 128;
    const int wm = wid & 1, wn = wid >> 1;
    const int nch = K >> 5;

    float acc[4][4][4];
    #pragma unroll
    for (int mt = 0; mt < 4; ++mt)
        #pragma unroll
        for (int nt = 0; nt < 4; ++nt)
            #pragma unroll
            for (int q = 0; q < 4; ++q) acc[mt][nt][q] = 0.f;

    const int lr = tid >> 2, lc = tid & 3;
    const f16* gAh = Ah + (size_t)(row0 + lr) * K + lc * 8;
    const f16* gBh = Bh + (size_t)(col0 + lr) * K + lc * 8;
    const uint32_t dst = lr * 80 + lc * 16;

    #define LOAD_CHUNK1(stg, k0) do {                                                  \
        uint32_t _b = s0 + (stg) * STAGEB1 + dst;                                      \
        CP_ASYNC16(_b,                   gAh + (k0));                                  \
        CP_ASYNC16(_b + 64 * 80,         gAh + (size_t)64 * K + (k0));                 \
        CP_ASYNC16(_b + TILEB,           gBh + (k0));                                  \
        CP_ASYNC16(_b + TILEB + 64 * 80, gBh + (size_t)64 * K + (k0));                 \
        CP_COMMIT();                                                                   \
    } while (0)

    LOAD_CHUNK1(0, 0);
    LOAD_CHUNK1(1, 32);

    const uint32_t a_row = (uint32_t)(wm * 64 + (lane & 15));
    const uint32_t a_coff = (uint32_t)((lane >> 4) * 8);
    const uint32_t b_row2 = (uint32_t)(wn * 32 + (lane & 7) + (((lane >> 4) & 1) << 3));
    const uint32_t b_coff = (uint32_t)(((lane >> 3) & 1) * 8);

    for (int ch = 0; ch < nch; ++ch) {
        if (ch + 1 < nch)
            asm volatile("cp.async.wait_group 1;" ::: "memory");
        else
            asm volatile("cp.async.wait_group 0;" ::: "memory");
        __syncthreads();
        if (ch + 2 < nch)
            LOAD_CHUNK1((ch + 2) % 3, (ch + 2) << 5);

        const uint32_t sb = s0 + (ch % 3) * STAGEB1;
        const uint32_t sAh_ = sb, sBh_ = sb + TILEB;
        #pragma unroll
        for (int ks = 0; ks < 2; ++ks) {
            const uint32_t acol = (ks * 16 + a_coff) * 2;
            const uint32_t bcol = (ks * 16 + b_coff) * 2;
            uint32_t afr[4][4], bfr[4][2];
            #pragma unroll
            for (int q = 0; q < 2; ++q) {
                uint32_t tmp[4];
                ldsm_x4(tmp, sBh_ + (b_row2 + q * 16) * 80 + bcol);
                bfr[2 * q][0] = tmp[0]; bfr[2 * q][1] = tmp[1];
                bfr[2 * q + 1][0] = tmp[2]; bfr[2 * q + 1][1] = tmp[3];
            }
            #pragma unroll
            for (int mt = 0; mt < 4; ++mt)
                ldsm_x4(afr[mt], sAh_ + (a_row + mt * 16) * 80 + acol);
            #pragma unroll
            for (int mt = 0; mt < 4; ++mt)
                #pragma unroll
                for (int nt = 0; nt < 4; ++nt)
                    mma16816(acc[mt][nt], afr[mt], bfr[nt]);
        }
    }

    const int er = lane >> 2, ec = (lane & 3) << 1;
    #pragma unroll
    for (int mt = 0; mt < 4; ++mt) {
        #pragma unroll
        for (int nt = 0; nt < 4; ++nt) {
            int gr = row0 + wm * 64 + mt * 16 + er;
            int gc = col0 + wn * 32 + nt * 8 + ec;
            const float* cc = acc[mt][nt];
            #pragma unroll
            for (int half = 0; half < 2; ++half) {
                int r = gr + half * 8;
                float v0 = cc[half * 2 + 0], v1 = cc[half * 2 + 1];
                if (mode == 2) {
                    v0 = geluf_(v0 + bias[gc]);
                    v1 = geluf_(v1 + bias[gc + 1]);
                    __half2 hp;
                    hp.x = __float2half_rn(v0);
                    hp.y = __float2half_rn(v1);
                    *(__half2*)(Oh + (size_t)r * N + gc) = hp;
                } else {
                    if (bias) { v0 += bias[gc]; v1 += bias[gc + 1]; }
                    if (res) {
                        const float* rp = res + (size_t)r * N + gc;
                        v0 += rp[0]; v1 += rp[1];
                    }
                    float2 v; v.x = v0; v.y = v1;
                    *(float2*)(C + (size_t)r * N + gc) = v;
                }
            }
        }
    }
}

// ---------------- fp16 3-product GEMM (high precision; in-proj tail) ----------------
#define STAGEB3 (4 * TILEB)
#define GEMM3_SMEM (2 * STAGEB3)
__global__ void __launch_bounds__(256, 2)
gemm_mma3(const f16* __restrict__ Ah, const f16* __restrict__ Al,
          const f16* __restrict__ Bh, const f16* __restrict__ Bl,
          float* __restrict__ C, int ldN, int K) {
    extern __shared__ __align__(16) f16 dsm[];
    const uint32_t s0 = smem_u32(dsm);
    const int tid = threadIdx.x, wid = tid >> 5, lane = tid & 31;
    const int row0 = blockIdx.y * 128, col0 = blockIdx.x * 128;
    const int wm = wid & 1, wn = wid >> 1;
    const int nch = K >> 5;

    float acc[4][4][4];
    #pragma unroll
    for (int mt = 0; mt < 4; ++mt)
        #pragma unroll
        for (int nt = 0; nt < 4; ++nt)
            #pragma unroll
            for (int q = 0; q < 4; ++q) acc[mt][nt][q] = 0.f;

    const int lr = tid >> 2, lc = tid & 3;
    const f16* gAh = Ah + (size_t)(row0 + lr) * K + lc * 8;
    const f16* gAl = Al + (size_t)(row0 + lr) * K + lc * 8;
    const f16* gBh = Bh + (size_t)(col0 + lr) * K + lc * 8;
    const f16* gBl = Bl + (size_t)(col0 + lr) * K + lc * 8;
    const uint32_t dst = lr * 80 + lc * 16;

    #define LOAD_CHUNK3(stg, k0) do {                                                  \
        uint32_t _b = s0 + (stg) * STAGEB3 + dst;                                      \
        CP_ASYNC16(_b,                       gAh + (k0));                              \
        CP_ASYNC16(_b + 64 * 80,             gAh + (size_t)64 * K + (k0));             \
        CP_ASYNC16(_b + TILEB,               gAl + (k0));                              \
        CP_ASYNC16(_b + TILEB + 64 * 80,     gAl + (size_t)64 * K + (k0));             \
        CP_ASYNC16(_b + 2 * TILEB,           gBh + (k0));                              \
        CP_ASYNC16(_b + 2 * TILEB + 64 * 80, gBh + (size_t)64 * K + (k0));             \
        CP_ASYNC16(_b + 3 * TILEB,           gBl + (k0));                              \
        CP_ASYNC16(_b + 3 * TILEB + 64 * 80, gBl + (size_t)64 * K + (k0));             \
        CP_COMMIT();                                                                   \
    } while (0)

    LOAD_CHUNK3(0, 0);

    const uint32_t a_row = (uint32_t)(wm * 64 + (lane & 15));
    const uint32_t a_coff = (uint32_t)((lane >> 4) * 8);
    const uint32_t b_row = (uint32_t)(wn * 32 + (lane & 7));
    const uint32_t b_coff = (uint32_t)(((lane >> 3) & 1) * 8);

    for (int ch = 0; ch < nch; ++ch) {
        const int stg = ch & 1;
        if (ch + 1 < nch) {
            LOAD_CHUNK3(stg ^ 1, (ch + 1) << 5);
            asm volatile("cp.async.wait_group 1;" ::: "memory");
        } else {
            asm volatile("cp.async.wait_group 0;" ::: "memory");
        }
        __syncthreads();

        const uint32_t sb = s0 + stg * STAGEB3;
        const uint32_t sAh_ = sb, sAl_ = sb + TILEB, sBh_ = sb + 2 * TILEB, sBl_ = sb + 3 * TILEB;
        #pragma unroll
        for (int ks = 0; ks < 2; ++ks) {
            const uint32_t acol = (ks * 16 + a_coff) * 2;
            const uint32_t bcol = (ks * 16 + b_coff) * 2;
            uint32_t afr[4][4], bh_[4][2], bl_[4][2];
            #pragma unroll
            for (int nt = 0; nt < 4; ++nt) {
                ldsm_x2(bh_[nt], sBh_ + (b_row + nt * 8) * 80 + bcol);
                ldsm_x2(bl_[nt], sBl_ + (b_row + nt * 8) * 80 + bcol);
            }
            #pragma unroll
            for (int mt = 0; mt < 4; ++mt)
                ldsm_x4(afr[mt], sAh_ + (a_row + mt * 16) * 80 + acol);
            #pragma unroll
            for (int mt = 0; mt < 4; ++mt)
                #pragma unroll
                for (int nt = 0; nt < 4; ++nt) {
                    mma16816(acc[mt][nt], afr[mt], bh_[nt]);
                    mma16816(acc[mt][nt], afr[mt], bl_[nt]);
                }
            #pragma unroll
            for (int mt = 0; mt < 4; ++mt)
                ldsm_x4(afr[mt], sAl_ + (a_row + mt * 16) * 80 + acol);
            #pragma unroll
            for (int mt = 0; mt < 4; ++mt)
                #pragma unroll
                for (int nt = 0; nt < 4; ++nt)
                    mma16816(acc[mt][nt], afr[mt], bh_[nt]);
        }
        __syncthreads();
    }

    const int er = lane >> 2, ec = (lane & 3) << 1;
    #pragma unroll
    for (int mt = 0; mt < 4; ++mt) {
        #pragma unroll
        for (int nt = 0; nt < 4; ++nt) {
            int gr = row0 + wm * 64 + mt * 16 + er;
            int gc = col0 + wn * 32 + nt * 8 + ec;
            const float* cc = acc[mt][nt];
            #pragma unroll
            for (int half = 0; half < 2; ++half) {
                int r = gr + half * 8;
                float2 v; v.x = cc[half * 2 + 0]; v.y = cc[half * 2 + 1];
                *(float2*)(C + (size_t)r * ldN + gc) = v;
            }
        }
    }
}

// ---------------- launch ----------------
extern "C" void kernel_launch(void* const* d_in, const int* in_sizes, int n_in,
                              void* d_out, int out_size) {
    const float* x       = (const float*)d_in[0];
    const float* w_in    = (const float*)d_in[1];
    const float* conv_w  = (const float*)d_in[2];
    const float* conv_b  = (const float*)d_in[3];
    const float* norm1_w = (const float*)d_in[4];
    const float* out_nw  = (const float*)d_in[5];
    const float* w_out   = (const float*)d_in[6];
    const float* norm2_w = (const float*)d_in[7];
    const float* ff_w1   = (const float*)d_in[8];
    const float* ff_b1   = (const float*)d_in[9];
    const float* ff_w2   = (const float*)d_in[10];
    const float* ff_b2   = (const float*)d_in[11];
    float* out = (float*)d_out;

    float *proj, *val, *par, *bcT, *scan, *x1;
    f16 *h1h, *h1l, *ygh, *h2h, *ffh;
    f16 *win, *wo, *w1, *w2, *wth, *wtl;
    cudaGetSymbolAddress((void**)&proj, g_proj);
    cudaGetSymbolAddress((void**)&val,  g_val);
    cudaGetSymbolAddress((void**)&par,  g_par);
    cudaGetSymbolAddress((void**)&bcT,  g_bcT);
    cudaGetSymbolAddress((void**)&scan, g_scan);
    cudaGetSymbolAddress((void**)&x1,   g_x1);
    cudaGetSymbolAddress((void**)&h1h,  g_h1h);  cudaGetSymbolAddress((void**)&h1l, g_h1l);
    cudaGetSymbolAddress((void**)&ygh,  g_ygh);
    cudaGetSymbolAddress((void**)&h2h,  g_h2h);
    cudaGetSymbolAddress((void**)&ffh,  g_ffh);
    cudaGetSymbolAddress((void**)&win,  g_win);
    cudaGetSymbolAddress((void**)&wo,   g_wo);
    cudaGetSymbolAddress((void**)&w1,   g_w1);
    cudaGetSymbolAddress((void**)&w2,   g_w2);
    cudaGetSymbolAddress((void**)&wth,  g_wth);
    cudaGetSymbolAddress((void**)&wtl,  g_wtl);

    cudaFuncSetAttribute(gemm_mma1, cudaFuncAttributeMaxDynamicSharedMemorySize, GEMM1_SMEM);
    cudaFuncSetAttribute(gemm_mma3, cudaFuncAttributeMaxDynamicSharedMemorySize, GEMM3_SMEM);

    // weight fp16 conversion (idempotent)
    cvt4_kernel<<<(PROJ_OUT * 1024 / 4 + 255) / 256, 256>>>((const float4*)w_in,
        (__half2*)win, PROJ_OUT * 1024 / 4);
    cvt4_kernel<<<(1024 * 2048 / 4 + 255) / 256, 256>>>((const float4*)w_out,
        (__half2*)wo, 1024 * 2048 / 4);
    cvt4_kernel<<<(4096 * 1024 / 4 + 255) / 256, 256>>>((const float4*)ff_w1,
        (__half2*)w1, 4096 * 1024 / 4);
    cvt4_kernel<<<(1024 * 4096 / 4 + 255) / 256, 256>>>((const float4*)ff_w2,
        (__half2*)w2, 1024 * 4096 / 4);
    // hi/lo split of w_in tail rows (scan-parameter columns)
    split4_kernel<<<(128 * 1024 / 4 + 255) / 256, 256>>>(
        (const float4*)(w_in + (size_t)4096 * 1024), (__half2*)wth, (__half2*)wtl, 128 * 1024 / 4);

    // 1. h1 = rmsnorm(x) (fp16 hi+lo; lo used only by the 3-product tail)
    rmsnorm_split_kernel<<<BT, 256>>>(x, norm1_w, h1h, h1l);
    // 2a. proj[:, :4096] = h1 @ w_in[:4096]^T  (1-product; gate/vraw tolerate fp16)
    gemm_mma1<<<dim3(32, BT / 128), 256, GEMM1_SMEM>>>(h1h, win, nullptr, nullptr,
                                                       proj, nullptr, PROJ_OUT, DMODEL, 1);
    // 2b. proj[:, 4096:] = h1 @ w_in[4096:]^T  (3-product, scan params)
    gemm_mma3<<<dim3(1, BT / 128), 256, GEMM3_SMEM>>>(h1h, h1l, wth, wtl,
                                                      proj + 4096, PROJ_OUT, DMODEL);
    // 3. fused conv+silu / params / bcpack
    prep_kernel<<<BT, 256>>>(proj, conv_w, conv_b, val, par, bcT);
    // 4. scan
    scan_kernel<<<2 * BQ * NHEADS, 512>>>(bcT, par, val, scan);
    // 5. yg = rmsnorm(scan * silu(gate)) (fp16 hi only)
    gated_norm_kernel<<<BT, 256>>>(proj, scan, out_nw, ygh);
    // 6. x1 = x + yg @ w_out^T  (1-product)
    gemm_mma1<<<dim3(DMODEL / 128, BT / 128), 256, GEMM1_SMEM>>>(ygh, wo, nullptr, x,
                                                    x1, nullptr, DMODEL, DINNER, 1);
    // 7. h2 = rmsnorm(x1) (fp16 hi only)
    rmsnorm_split_kernel<<<BT, 256>>>(x1, norm2_w, h2h, nullptr);
    // 8. ffh = fp16(gelu(h2 @ ff_w1^T + b1))  (1-product)
    gemm_mma1<<<dim3(DFF / 128, BT / 128), 256, GEMM1_SMEM>>>(h2h, w1, ff_b1, nullptr,
                                                 nullptr, ffh, DFF, DMODEL, 2);
    // 9. out = x1 + ffh @ ff_w2^T + b2  (1-product)
    gemm_mma1<<<dim3(DMODEL / 128, BT / 128), 256, GEMM1_SMEM>>>(ffh, w2, ff_b2, x1,
                                                    out, nullptr, DMODEL, DFF, 1);
}